// round 1
// baseline (speedup 1.0000x reference)
#include <cuda_runtime.h>
#include <math.h>

#define B_    64
#define SEQ   257          // S+1 rows per batch in h
#define S_    256
#define D_    768
#define F_    3072
#define HEADS 12
#define DKH   64
#define ROWS  (B_*SEQ)     // 16448
#define BSR   (B_*S_)      // 16384

// ---------------- scratch (static device globals; no allocation) ----------------
__device__ float g_h[(size_t)ROWS*D_];
__device__ float g_q[(size_t)ROWS*D_];
__device__ float g_k[(size_t)ROWS*D_];
__device__ float g_v[(size_t)ROWS*D_];
__device__ float g_o[(size_t)ROWS*D_];
__device__ float g_t[(size_t)ROWS*D_];
__device__ float g_f[(size_t)ROWS*F_];

__device__ __forceinline__ float gelu_f(float x) {
    float x3 = x * x * x;
    float t = tanhf(0.7978845608028654f * (x + 0.044715f * x3));
    return 0.5f * x * (1.0f + t);
}

// ---------------- SGEMM: C = A(MxK,row) @ B(KxN,row) + bias, optional GELU ----------------
// 128x128 tile, BK=8, 256 threads, 8x8 per thread (split 4+4 halves for conflict-free LDS.128)
template<int ACT>
__global__ void __launch_bounds__(256)
sgemm_kernel(const float* __restrict__ A, const float* __restrict__ B,
             const float* __restrict__ bias, float* __restrict__ C,
             int M, int N, int K)
{
    __shared__ float As[8][128];
    __shared__ float Bs[8][128];

    const int tid = threadIdx.x;
    const int bm  = blockIdx.y * 128;
    const int bn  = blockIdx.x * 128;

    const int arow = tid >> 1;
    const int acol = (tid & 1) << 2;
    const int brow = tid >> 5;
    const int bcol = (tid & 31) << 2;
    const int tx = tid & 15;
    const int ty = tid >> 4;

    float acc[8][8];
#pragma unroll
    for (int i = 0; i < 8; i++)
#pragma unroll
        for (int j = 0; j < 8; j++) acc[i][j] = 0.f;

    const int  ga     = bm + arow;
    const bool avalid = (ga < M);
    const float* Aptr = A + (size_t)(avalid ? ga : 0) * K + acol;
    const float* Bptr = B + (size_t)brow * N + bn + bcol;

    for (int k0 = 0; k0 < K; k0 += 8) {
        float4 av = avalid ? *(const float4*)(Aptr + k0)
                           : make_float4(0.f, 0.f, 0.f, 0.f);
        As[acol + 0][arow] = av.x;
        As[acol + 1][arow] = av.y;
        As[acol + 2][arow] = av.z;
        As[acol + 3][arow] = av.w;
        *(float4*)&Bs[brow][bcol] = *(const float4*)(Bptr + (size_t)k0 * N);
        __syncthreads();

#pragma unroll
        for (int kk = 0; kk < 8; kk++) {
            float4 a0 = *(const float4*)&As[kk][ty * 4];
            float4 a1 = *(const float4*)&As[kk][64 + ty * 4];
            float4 b0 = *(const float4*)&Bs[kk][tx * 4];
            float4 b1 = *(const float4*)&Bs[kk][64 + tx * 4];
            float a[8] = {a0.x, a0.y, a0.z, a0.w, a1.x, a1.y, a1.z, a1.w};
            float b[8] = {b0.x, b0.y, b0.z, b0.w, b1.x, b1.y, b1.z, b1.w};
#pragma unroll
            for (int i = 0; i < 8; i++)
#pragma unroll
                for (int j = 0; j < 8; j++)
                    acc[i][j] += a[i] * b[j];
        }
        __syncthreads();
    }

    float4 bias0 = *(const float4*)&bias[bn + tx * 4];
    float4 bias1 = *(const float4*)&bias[bn + 64 + tx * 4];
    float bv[8] = {bias0.x, bias0.y, bias0.z, bias0.w,
                   bias1.x, bias1.y, bias1.z, bias1.w};

#pragma unroll
    for (int i = 0; i < 8; i++) {
        int r = bm + ((i < 4) ? (ty * 4 + i) : (64 + ty * 4 + (i - 4)));
        if (r >= M) continue;
        float out[8];
#pragma unroll
        for (int j = 0; j < 8; j++) {
            float vv = acc[i][j] + bv[j];
            if (ACT == 1) vv = gelu_f(vv);
            out[j] = vv;
        }
        float* cp = C + (size_t)r * N;
        *(float4*)&cp[bn + tx * 4]      = make_float4(out[0], out[1], out[2], out[3]);
        *(float4*)&cp[bn + 64 + tx * 4] = make_float4(out[4], out[5], out[6], out[7]);
    }
}

// ---------------- assemble h: masking + shuffle gather + pos emb + agg token ----------------
__global__ void assemble_kernel(const float* __restrict__ x,          // [16384,768]
                                const float* __restrict__ rnd,        // [16384,3]
                                const int*   __restrict__ perm,       // [16384]
                                const float* __restrict__ mask_tok,
                                const float* __restrict__ agg_tok,
                                const float* __restrict__ pos_emb,    // [300,768]
                                float* __restrict__ h,                // [16448,768]
                                float* __restrict__ mask_pos)         // [16384]
{
    int row = blockIdx.x;
    int b   = row / SEQ;
    int sp  = row - b * SEQ;
    int tid = threadIdx.x;
    float* hp = h + (size_t)row * D_;

    if (sp == 0) {
        hp[tid]       = agg_tok[tid];
        hp[tid + 256] = agg_tok[tid + 256];
        hp[tid + 512] = agg_tok[tid + 512];
        return;
    }
    int s = sp - 1;
    int i = b * S_ + s;
    float r0 = rnd[i * 3 + 0];
    float r1 = rnd[i * 3 + 1];
    float r2 = rnd[i * 3 + 2];
    bool  sel = (r0 <= 0.2f);
    float m  = (sel && r1 <= 0.8f) ? 1.f : 0.f;
    float rd = (sel && r1 > 0.8f && r2 <= 0.5f) ? 1.f : 0.f;
    if (tid == 0) mask_pos[i] = sel ? 1.f : 0.f;

    int pi = perm[i];
    const float* xp = x + (size_t)i  * D_;
    const float* sh = x + (size_t)pi * D_;
    const float* pe = pos_emb + (size_t)s * D_;
    float keep = 1.f - m - rd;

#pragma unroll
    for (int e = 0; e < 3; e++) {
        int d = tid + e * 256;
        hp[d] = xp[d] * keep + mask_tok[d] * m + sh[d] * rd + pe[d];
    }
}

// ---------------- attention: one block per (head, batch) ----------------
// smem: Kt[64][257] + V[257][64] + probs[8][257] + qbuf[8][64]
__global__ void __launch_bounds__(256)
attn_kernel(const float* __restrict__ Q, const float* __restrict__ K,
            const float* __restrict__ V, float* __restrict__ O)
{
    extern __shared__ float sm[];
    float* Kt    = sm;                         // 64*257
    float* Vs    = Kt + 64 * 257;              // 257*64
    float* probs = Vs + 257 * 64;              // 8*257
    float* qbuf  = probs + 8 * 257;            // 8*64

    int hh = blockIdx.x;
    int bb = blockIdx.y;
    int tid = threadIdx.x;
    const size_t base = ((size_t)bb * SEQ) * D_ + (size_t)hh * DKH;

    for (int idx = tid; idx < SEQ * DKH; idx += 256) {
        int k = idx >> 6;
        int d = idx & 63;
        float kv = K[base + (size_t)k * D_ + d];
        Kt[d * SEQ + k] = kv;
        Vs[idx] = V[base + (size_t)k * D_ + d];
    }
    __syncthreads();

    int w = tid >> 5, lane = tid & 31;
    float* qw = qbuf + w * 64;
    float* pw = probs + w * SEQ;

    for (int q = w; q < SEQ; q += 8) {
        const float* qp = Q + base + (size_t)q * D_;
        qw[lane]      = qp[lane];
        qw[lane + 32] = qp[lane + 32];
        __syncwarp();

        float s[9];
        float mx = -1e30f;
#pragma unroll
        for (int j = 0; j < 9; j++) {
            int k = lane + j * 32;
            float acc = -1e30f;
            if (k < SEQ) {
                acc = 0.f;
                for (int d = 0; d < 64; d++)
                    acc += qw[d] * Kt[d * SEQ + k];
                acc *= 0.125f;  // 1/sqrt(64)
                mx = fmaxf(mx, acc);
            }
            s[j] = acc;
        }
        for (int off = 16; off; off >>= 1)
            mx = fmaxf(mx, __shfl_xor_sync(0xffffffffu, mx, off));

        float sum = 0.f;
#pragma unroll
        for (int j = 0; j < 9; j++) {
            int k = lane + j * 32;
            float e = 0.f;
            if (k < SEQ) { e = expf(s[j] - mx); sum += e; }
            s[j] = e;
        }
        for (int off = 16; off; off >>= 1)
            sum += __shfl_xor_sync(0xffffffffu, sum, off);
        float inv = 1.f / sum;
#pragma unroll
        for (int j = 0; j < 9; j++) {
            int k = lane + j * 32;
            if (k < SEQ) pw[k] = s[j] * inv;
        }
        __syncwarp();

        float o0 = 0.f, o1 = 0.f;
        for (int k = 0; k < SEQ; k++) {
            float p = pw[k];
            float2 v2 = *(const float2*)&Vs[k * 64 + 2 * lane];
            o0 += p * v2.x;
            o1 += p * v2.y;
        }
        *(float2*)&O[base + (size_t)q * D_ + 2 * lane] = make_float2(o0, o1);
        __syncwarp();
    }
}

// ---------------- residual + LayerNorm (in place ok: block owns its row) ----------------
__global__ void add_ln_kernel(const float* __restrict__ H, const float* __restrict__ Dl,
                              const float* __restrict__ g, const float* __restrict__ be,
                              float* __restrict__ Out)
{
    int row = blockIdx.x, tid = threadIdx.x;
    const float* hp = H  + (size_t)row * D_;
    const float* dp = Dl + (size_t)row * D_;
    float v0 = hp[tid]       + dp[tid];
    float v1 = hp[tid + 256] + dp[tid + 256];
    float v2 = hp[tid + 512] + dp[tid + 512];

    __shared__ float red[8];
    __shared__ float s_mu, s_var;
    int lane = tid & 31, w = tid >> 5;

    float s = v0 + v1 + v2;
    for (int off = 16; off; off >>= 1) s += __shfl_xor_sync(0xffffffffu, s, off);
    if (lane == 0) red[w] = s;
    __syncthreads();
    if (tid == 0) {
        float t = 0.f;
        for (int i = 0; i < 8; i++) t += red[i];
        s_mu = t * (1.0f / 768.0f);
    }
    __syncthreads();
    float mu = s_mu;
    float d0 = v0 - mu, d1 = v1 - mu, d2 = v2 - mu;
    float qv = d0 * d0 + d1 * d1 + d2 * d2;
    for (int off = 16; off; off >>= 1) qv += __shfl_xor_sync(0xffffffffu, qv, off);
    if (lane == 0) red[w] = qv;
    __syncthreads();
    if (tid == 0) {
        float t = 0.f;
        for (int i = 0; i < 8; i++) t += red[i];
        s_var = t * (1.0f / 768.0f);
    }
    __syncthreads();
    float rs = rsqrtf(s_var + 1e-6f);

    float* op = Out + (size_t)row * D_;
    op[tid]       = d0 * rs * g[tid]       + be[tid];
    op[tid + 256] = d1 * rs * g[tid + 256] + be[tid + 256];
    op[tid + 512] = d2 * rs * g[tid + 512] + be[tid + 512];
}

// ---------------- scatter h -> aggregated + predictions ----------------
__global__ void writeout_kernel(const float* __restrict__ h,
                                float* __restrict__ agg, float* __restrict__ pred)
{
    size_t idx = (size_t)blockIdx.x * 256 + threadIdx.x;
    if (idx >= (size_t)ROWS * D_) return;
    int row = (int)(idx / D_);
    int d   = (int)(idx - (size_t)row * D_);
    int b   = row / SEQ;
    int sp  = row - b * SEQ;
    float val = h[idx];
    if (sp == 0) agg[(size_t)b * D_ + d] = val;
    else pred[((size_t)(b * S_ + sp - 1)) * D_ + d] = val;
}

// ---------------- host ----------------
static inline void run_sgemm(const float* A, const float* Bm, const float* bias,
                             float* C, int M, int N, int K, bool gelu)
{
    dim3 grid(N / 128, (M + 127) / 128);
    if (gelu) sgemm_kernel<1><<<grid, 256>>>(A, Bm, bias, C, M, N, K);
    else      sgemm_kernel<0><<<grid, 256>>>(A, Bm, bias, C, M, N, K);
}

extern "C" void kernel_launch(void* const* d_in, const int* in_sizes, int n_in,
                              void* d_out, int out_size)
{
    const float* inputs     = (const float*)d_in[0];
    const float* randomness = (const float*)d_in[1];
    const int*   perm       = (const int*)  d_in[2];
    const float* conv_w     = (const float*)d_in[3];
    const float* conv_b     = (const float*)d_in[4];
    const float* pos_emb    = (const float*)d_in[5];
    const float* mask_tok   = (const float*)d_in[6];
    const float* agg_tok    = (const float*)d_in[7];
    const float* wq  = (const float*)d_in[8];
    const float* bq  = (const float*)d_in[9];
    const float* wk  = (const float*)d_in[10];
    const float* bk  = (const float*)d_in[11];
    const float* wv  = (const float*)d_in[12];
    const float* bv  = (const float*)d_in[13];
    const float* wo  = (const float*)d_in[14];
    const float* bo  = (const float*)d_in[15];
    const float* ln1g = (const float*)d_in[16];
    const float* ln1b = (const float*)d_in[17];
    const float* w1  = (const float*)d_in[18];
    const float* b1  = (const float*)d_in[19];
    const float* w2  = (const float*)d_in[20];
    const float* b2  = (const float*)d_in[21];
    const float* ln2g = (const float*)d_in[22];
    const float* ln2b = (const float*)d_in[23];

    float* out      = (float*)d_out;
    float* out_agg  = out;                       // 64*768
    float* out_pred = out + 49152;               // 64*256*768
    float* out_mask = out + 12632064;            // 64*256
    float* out_emb  = out + 12648448;            // 64*256*768

    float *h, *q, *k, *v, *o, *t, *f;
    cudaGetSymbolAddress((void**)&h, g_h);
    cudaGetSymbolAddress((void**)&q, g_q);
    cudaGetSymbolAddress((void**)&k, g_k);
    cudaGetSymbolAddress((void**)&v, g_v);
    cudaGetSymbolAddress((void**)&o, g_o);
    cudaGetSymbolAddress((void**)&t, g_t);
    cudaGetSymbolAddress((void**)&f, g_f);

    // conv (stride == kernel => pure GEMM), writes embeddings output directly
    run_sgemm(inputs, conv_w, conv_b, out_emb, BSR, D_, 512, false);

    // build h (mask/shuffle/pos-emb/agg token) + mask_pos output
    assemble_kernel<<<ROWS, 256>>>(out_emb, randomness, perm, mask_tok, agg_tok,
                                   pos_emb, h, out_mask);

    const int SMEM_ATTN = (64 * SEQ + SEQ * 64 + 8 * SEQ + 8 * 64) * (int)sizeof(float);
    cudaFuncSetAttribute(attn_kernel, cudaFuncAttributeMaxDynamicSharedMemorySize, SMEM_ATTN);

    for (int l = 0; l < 2; l++) {
        size_t wOff = (size_t)l * D_ * D_;
        run_sgemm(h, wq + wOff, bq + l * D_, q, ROWS, D_, D_, false);
        run_sgemm(h, wk + wOff, bk + l * D_, k, ROWS, D_, D_, false);
        run_sgemm(h, wv + wOff, bv + l * D_, v, ROWS, D_, D_, false);

        attn_kernel<<<dim3(HEADS, B_), 256, SMEM_ATTN>>>(q, k, v, o);

        run_sgemm(o, wo + wOff, bo + l * D_, t, ROWS, D_, D_, false);
        add_ln_kernel<<<ROWS, 256>>>(h, t, ln1g + l * D_, ln1b + l * D_, h);

        run_sgemm(h, w1 + (size_t)l * D_ * F_, b1 + l * F_, f, ROWS, F_, D_, true);
        run_sgemm(f, w2 + (size_t)l * F_ * D_, b2 + l * D_, t, ROWS, D_, F_, false);
        add_ln_kernel<<<ROWS, 256>>>(h, t, ln2g + l * D_, ln2b + l * D_, h);
    }

    int total = ROWS * D_;
    writeout_kernel<<<(total + 255) / 256, 256>>>(h, out_agg, out_pred);
}

// round 2
// speedup vs baseline: 1.8126x; 1.8126x over previous
#include <cuda_runtime.h>
#include <math.h>
#include <stdint.h>

#define B_    64
#define SEQ   257          // S+1 rows per batch in h
#define S_    256
#define D_    768
#define F_    3072
#define HEADS 12
#define DKH   64
#define ROWS  (B_*SEQ)     // 16448
#define BSR   (B_*S_)      // 16384

// ---------------- scratch (static device globals; no allocation) ----------------
__device__ float g_h[(size_t)ROWS*D_];
__device__ float g_q[(size_t)ROWS*D_];
__device__ float g_k[(size_t)ROWS*D_];
__device__ float g_v[(size_t)ROWS*D_];
__device__ float g_o[(size_t)ROWS*D_];
__device__ float g_t[(size_t)ROWS*D_];
__device__ float g_f[(size_t)ROWS*F_];

__device__ __forceinline__ float gelu_f(float x) {
    float x3 = x * x * x;
    float t = tanhf(0.7978845608028654f * (x + 0.044715f * x3));
    return 0.5f * x * (1.0f + t);
}

__device__ __forceinline__ uint32_t f2tf(float x) {
    uint32_t u;
    asm("cvt.rna.tf32.f32 %0, %1;" : "=r"(u) : "f"(x));
    return u;
}

// ---------------- TF32 tensor-core GEMM ----------------
// C = A(MxK,row) @ B(KxN,row) + bias, optional GELU.
// 128x128 block tile, BK=16, 256 threads (8 warps, 4x2), warp tile 32x64,
// mma.sync.m16n8k8 tf32, fp32 accumulate, double-buffered smem,
// RNA f32->tf32 conversion on the global->smem path.
template<int ACT>
__global__ void __launch_bounds__(256, 2)
tgemm_kernel(const float* __restrict__ A, const float* __restrict__ Bm,
             const float* __restrict__ bias, float* __restrict__ C,
             int M, int N, int K)
{
    __shared__ uint32_t As[2][16][132];   // [k][m]
    __shared__ uint32_t Bs[2][16][132];   // [k][n]

    const int tid  = threadIdx.x;
    const int bm   = blockIdx.y * 128;
    const int bn   = blockIdx.x * 128;
    const int wid  = tid >> 5;
    const int lane = tid & 31;
    const int wm   = (wid & 3) * 32;      // warp m offset in tile
    const int wn   = (wid >> 2) * 64;     // warp n offset in tile
    const int g    = lane >> 2;           // groupID
    const int tig  = lane & 3;            // thread in group

    float acc[2][8][4];
#pragma unroll
    for (int i = 0; i < 2; i++)
#pragma unroll
        for (int j = 0; j < 8; j++)
#pragma unroll
            for (int c = 0; c < 4; c++) acc[i][j][c] = 0.f;

    // A staging: 2 float4 per thread. rows ar, ar+64; cols ac..ac+3
    const int ar = tid >> 2;
    const int ac = (tid & 3) << 2;
    const bool av0 = (bm + ar)      < M;
    const bool av1 = (bm + ar + 64) < M;
    const float* Ap0 = A + (size_t)(av0 ? (bm + ar)      : 0) * K + ac;
    const float* Ap1 = A + (size_t)(av1 ? (bm + ar + 64) : 0) * K + ac;

    // B staging: 2 float4 per thread. rows bk, bk+8; cols bc..bc+3
    const int bk = tid >> 5;
    const int bc = lane << 2;
    const float* Bp0 = Bm + (size_t)bk       * N + bn + bc;
    const float* Bp1 = Bm + (size_t)(bk + 8) * N + bn + bc;

    const int nk = K / 16;
    const float4 z4 = make_float4(0.f, 0.f, 0.f, 0.f);

    // prologue: load tile 0
    {
        float4 a0 = av0 ? *(const float4*)Ap0 : z4;
        float4 a1 = av1 ? *(const float4*)Ap1 : z4;
        float4 b0 = *(const float4*)Bp0;
        float4 b1 = *(const float4*)Bp1;
        As[0][ac + 0][ar] = f2tf(a0.x); As[0][ac + 1][ar] = f2tf(a0.y);
        As[0][ac + 2][ar] = f2tf(a0.z); As[0][ac + 3][ar] = f2tf(a0.w);
        As[0][ac + 0][ar + 64] = f2tf(a1.x); As[0][ac + 1][ar + 64] = f2tf(a1.y);
        As[0][ac + 2][ar + 64] = f2tf(a1.z); As[0][ac + 3][ar + 64] = f2tf(a1.w);
        uint4 cb0 = make_uint4(f2tf(b0.x), f2tf(b0.y), f2tf(b0.z), f2tf(b0.w));
        uint4 cb1 = make_uint4(f2tf(b1.x), f2tf(b1.y), f2tf(b1.z), f2tf(b1.w));
        *(uint4*)&Bs[0][bk][bc]     = cb0;
        *(uint4*)&Bs[0][bk + 8][bc] = cb1;
    }
    __syncthreads();

    for (int kt = 0; kt < nk; kt++) {
        const int cur = kt & 1;

        // prefetch next tile into registers
        float4 na0, na1, nb0, nb1;
        const bool have_next = (kt + 1 < nk);
        if (have_next) {
            const int off = (kt + 1) * 16;
            na0 = av0 ? *(const float4*)(Ap0 + off) : z4;
            na1 = av1 ? *(const float4*)(Ap1 + off) : z4;
            nb0 = *(const float4*)(Bp0 + (size_t)off * N);
            nb1 = *(const float4*)(Bp1 + (size_t)off * N);
        }

        // compute on current buffer
#pragma unroll
        for (int kk = 0; kk < 2; kk++) {
            const int k0 = kk * 8;
            uint32_t af[2][4], bf[8][2];
#pragma unroll
            for (int i = 0; i < 2; i++) {
                const int m0 = wm + i * 16 + g;
                af[i][0] = As[cur][k0 + tig][m0];
                af[i][1] = As[cur][k0 + tig][m0 + 8];
                af[i][2] = As[cur][k0 + tig + 4][m0];
                af[i][3] = As[cur][k0 + tig + 4][m0 + 8];
            }
#pragma unroll
            for (int j = 0; j < 8; j++) {
                const int n0 = wn + j * 8 + g;
                bf[j][0] = Bs[cur][k0 + tig][n0];
                bf[j][1] = Bs[cur][k0 + tig + 4][n0];
            }
#pragma unroll
            for (int i = 0; i < 2; i++)
#pragma unroll
                for (int j = 0; j < 8; j++) {
                    asm volatile(
                        "mma.sync.aligned.m16n8k8.row.col.f32.tf32.tf32.f32 "
                        "{%0,%1,%2,%3}, {%4,%5,%6,%7}, {%8,%9}, {%0,%1,%2,%3};"
                        : "+f"(acc[i][j][0]), "+f"(acc[i][j][1]),
                          "+f"(acc[i][j][2]), "+f"(acc[i][j][3])
                        : "r"(af[i][0]), "r"(af[i][1]), "r"(af[i][2]), "r"(af[i][3]),
                          "r"(bf[j][0]), "r"(bf[j][1]));
                }
        }

        // stage next tile into the other buffer
        if (have_next) {
            const int nxt = cur ^ 1;
            As[nxt][ac + 0][ar] = f2tf(na0.x); As[nxt][ac + 1][ar] = f2tf(na0.y);
            As[nxt][ac + 2][ar] = f2tf(na0.z); As[nxt][ac + 3][ar] = f2tf(na0.w);
            As[nxt][ac + 0][ar + 64] = f2tf(na1.x); As[nxt][ac + 1][ar + 64] = f2tf(na1.y);
            As[nxt][ac + 2][ar + 64] = f2tf(na1.z); As[nxt][ac + 3][ar + 64] = f2tf(na1.w);
            uint4 cb0 = make_uint4(f2tf(nb0.x), f2tf(nb0.y), f2tf(nb0.z), f2tf(nb0.w));
            uint4 cb1 = make_uint4(f2tf(nb1.x), f2tf(nb1.y), f2tf(nb1.z), f2tf(nb1.w));
            *(uint4*)&Bs[nxt][bk][bc]     = cb0;
            *(uint4*)&Bs[nxt][bk + 8][bc] = cb1;
        }
        __syncthreads();
    }

    // epilogue: bias (+GELU), float2 stores
#pragma unroll
    for (int i = 0; i < 2; i++) {
        const int r0 = bm + wm + i * 16 + g;
        const int r1 = r0 + 8;
#pragma unroll
        for (int j = 0; j < 8; j++) {
            const int col = bn + wn + j * 8 + 2 * tig;
            const float bv0 = bias[col];
            const float bv1 = bias[col + 1];
            float v0 = acc[i][j][0] + bv0;
            float v1 = acc[i][j][1] + bv1;
            float v2 = acc[i][j][2] + bv0;
            float v3 = acc[i][j][3] + bv1;
            if (ACT == 1) { v0 = gelu_f(v0); v1 = gelu_f(v1); v2 = gelu_f(v2); v3 = gelu_f(v3); }
            if (r0 < M) *(float2*)&C[(size_t)r0 * N + col] = make_float2(v0, v1);
            if (r1 < M) *(float2*)&C[(size_t)r1 * N + col] = make_float2(v2, v3);
        }
    }
}

// ---------------- assemble h: masking + shuffle gather + pos emb + agg token ----------------
__global__ void assemble_kernel(const float* __restrict__ x,
                                const float* __restrict__ rnd,
                                const int*   __restrict__ perm,
                                const float* __restrict__ mask_tok,
                                const float* __restrict__ agg_tok,
                                const float* __restrict__ pos_emb,
                                float* __restrict__ h,
                                float* __restrict__ mask_pos)
{
    int row = blockIdx.x;
    int b   = row / SEQ;
    int sp  = row - b * SEQ;
    int tid = threadIdx.x;
    float* hp = h + (size_t)row * D_;

    if (sp == 0) {
        hp[tid]       = agg_tok[tid];
        hp[tid + 256] = agg_tok[tid + 256];
        hp[tid + 512] = agg_tok[tid + 512];
        return;
    }
    int s = sp - 1;
    int i = b * S_ + s;
    float r0 = rnd[i * 3 + 0];
    float r1 = rnd[i * 3 + 1];
    float r2 = rnd[i * 3 + 2];
    bool  sel = (r0 <= 0.2f);
    float m  = (sel && r1 <= 0.8f) ? 1.f : 0.f;
    float rd = (sel && r1 > 0.8f && r2 <= 0.5f) ? 1.f : 0.f;
    if (tid == 0) mask_pos[i] = sel ? 1.f : 0.f;

    int pi = perm[i];
    const float* xp = x + (size_t)i  * D_;
    const float* sh = x + (size_t)pi * D_;
    const float* pe = pos_emb + (size_t)s * D_;
    float keep = 1.f - m - rd;

#pragma unroll
    for (int e = 0; e < 3; e++) {
        int d = tid + e * 256;
        hp[d] = xp[d] * keep + mask_tok[d] * m + sh[d] * rd + pe[d];
    }
}

// ---------------- attention: one block per (head, batch) ----------------
__global__ void __launch_bounds__(256)
attn_kernel(const float* __restrict__ Q, const float* __restrict__ K,
            const float* __restrict__ V, float* __restrict__ O)
{
    extern __shared__ float sm[];
    float* Kt    = sm;                         // 64*257
    float* Vs    = Kt + 64 * 257;              // 257*64
    float* probs = Vs + 257 * 64;              // 8*257
    float* qbuf  = probs + 8 * 257;            // 8*64

    int hh = blockIdx.x;
    int bb = blockIdx.y;
    int tid = threadIdx.x;
    const size_t base = ((size_t)bb * SEQ) * D_ + (size_t)hh * DKH;

    for (int idx = tid; idx < SEQ * DKH; idx += 256) {
        int k = idx >> 6;
        int d = idx & 63;
        float kv = K[base + (size_t)k * D_ + d];
        Kt[d * SEQ + k] = kv;
        Vs[idx] = V[base + (size_t)k * D_ + d];
    }
    __syncthreads();

    int w = tid >> 5, lane = tid & 31;
    float* qw = qbuf + w * 64;
    float* pw = probs + w * SEQ;

    for (int q = w; q < SEQ; q += 8) {
        const float* qp = Q + base + (size_t)q * D_;
        qw[lane]      = qp[lane];
        qw[lane + 32] = qp[lane + 32];
        __syncwarp();

        float s[9];
        float mx = -1e30f;
#pragma unroll
        for (int j = 0; j < 9; j++) {
            int k = lane + j * 32;
            float acc = -1e30f;
            if (k < SEQ) {
                acc = 0.f;
                for (int d = 0; d < 64; d++)
                    acc += qw[d] * Kt[d * SEQ + k];
                acc *= 0.125f;
                mx = fmaxf(mx, acc);
            }
            s[j] = acc;
        }
        for (int off = 16; off; off >>= 1)
            mx = fmaxf(mx, __shfl_xor_sync(0xffffffffu, mx, off));

        float sum = 0.f;
#pragma unroll
        for (int j = 0; j < 9; j++) {
            int k = lane + j * 32;
            float e = 0.f;
            if (k < SEQ) { e = expf(s[j] - mx); sum += e; }
            s[j] = e;
        }
        for (int off = 16; off; off >>= 1)
            sum += __shfl_xor_sync(0xffffffffu, sum, off);
        float inv = 1.f / sum;
#pragma unroll
        for (int j = 0; j < 9; j++) {
            int k = lane + j * 32;
            if (k < SEQ) pw[k] = s[j] * inv;
        }
        __syncwarp();

        float o0 = 0.f, o1 = 0.f;
        for (int k = 0; k < SEQ; k++) {
            float p = pw[k];
            float2 v2 = *(const float2*)&Vs[k * 64 + 2 * lane];
            o0 += p * v2.x;
            o1 += p * v2.y;
        }
        *(float2*)&O[base + (size_t)q * D_ + 2 * lane] = make_float2(o0, o1);
        __syncwarp();
    }
}

// ---------------- residual + LayerNorm ----------------
__global__ void add_ln_kernel(const float* __restrict__ H, const float* __restrict__ Dl,
                              const float* __restrict__ g, const float* __restrict__ be,
                              float* __restrict__ Out)
{
    int row = blockIdx.x, tid = threadIdx.x;
    const float* hp = H  + (size_t)row * D_;
    const float* dp = Dl + (size_t)row * D_;
    float v0 = hp[tid]       + dp[tid];
    float v1 = hp[tid + 256] + dp[tid + 256];
    float v2 = hp[tid + 512] + dp[tid + 512];

    __shared__ float red[8];
    __shared__ float s_mu, s_var;
    int lane = tid & 31, w = tid >> 5;

    float s = v0 + v1 + v2;
    for (int off = 16; off; off >>= 1) s += __shfl_xor_sync(0xffffffffu, s, off);
    if (lane == 0) red[w] = s;
    __syncthreads();
    if (tid == 0) {
        float t = 0.f;
        for (int i = 0; i < 8; i++) t += red[i];
        s_mu = t * (1.0f / 768.0f);
    }
    __syncthreads();
    float mu = s_mu;
    float d0 = v0 - mu, d1 = v1 - mu, d2 = v2 - mu;
    float qv = d0 * d0 + d1 * d1 + d2 * d2;
    for (int off = 16; off; off >>= 1) qv += __shfl_xor_sync(0xffffffffu, qv, off);
    if (lane == 0) red[w] = qv;
    __syncthreads();
    if (tid == 0) {
        float t = 0.f;
        for (int i = 0; i < 8; i++) t += red[i];
        s_var = t * (1.0f / 768.0f);
    }
    __syncthreads();
    float rs = rsqrtf(s_var + 1e-6f);

    float* op = Out + (size_t)row * D_;
    op[tid]       = d0 * rs * g[tid]       + be[tid];
    op[tid + 256] = d1 * rs * g[tid + 256] + be[tid + 256];
    op[tid + 512] = d2 * rs * g[tid + 512] + be[tid + 512];
}

// ---------------- scatter h -> aggregated + predictions ----------------
__global__ void writeout_kernel(const float* __restrict__ h,
                                float* __restrict__ agg, float* __restrict__ pred)
{
    size_t idx = (size_t)blockIdx.x * 256 + threadIdx.x;
    if (idx >= (size_t)ROWS * D_) return;
    int row = (int)(idx / D_);
    int d   = (int)(idx - (size_t)row * D_);
    int b   = row / SEQ;
    int sp  = row - b * SEQ;
    float val = h[idx];
    if (sp == 0) agg[(size_t)b * D_ + d] = val;
    else pred[((size_t)(b * S_ + sp - 1)) * D_ + d] = val;
}

// ---------------- host ----------------
static inline void run_gemm(const float* A, const float* Bm, const float* bias,
                            float* C, int M, int N, int K, bool gelu)
{
    dim3 grid(N / 128, (M + 127) / 128);
    if (gelu) tgemm_kernel<1><<<grid, 256>>>(A, Bm, bias, C, M, N, K);
    else      tgemm_kernel<0><<<grid, 256>>>(A, Bm, bias, C, M, N, K);
}

extern "C" void kernel_launch(void* const* d_in, const int* in_sizes, int n_in,
                              void* d_out, int out_size)
{
    const float* inputs     = (const float*)d_in[0];
    const float* randomness = (const float*)d_in[1];
    const int*   perm       = (const int*)  d_in[2];
    const float* conv_w     = (const float*)d_in[3];
    const float* conv_b     = (const float*)d_in[4];
    const float* pos_emb    = (const float*)d_in[5];
    const float* mask_tok   = (const float*)d_in[6];
    const float* agg_tok    = (const float*)d_in[7];
    const float* wq  = (const float*)d_in[8];
    const float* bq  = (const float*)d_in[9];
    const float* wk  = (const float*)d_in[10];
    const float* bk  = (const float*)d_in[11];
    const float* wv  = (const float*)d_in[12];
    const float* bv  = (const float*)d_in[13];
    const float* wo  = (const float*)d_in[14];
    const float* bo  = (const float*)d_in[15];
    const float* ln1g = (const float*)d_in[16];
    const float* ln1b = (const float*)d_in[17];
    const float* w1  = (const float*)d_in[18];
    const float* b1  = (const float*)d_in[19];
    const float* w2  = (const float*)d_in[20];
    const float* b2  = (const float*)d_in[21];
    const float* ln2g = (const float*)d_in[22];
    const float* ln2b = (const float*)d_in[23];

    float* out      = (float*)d_out;
    float* out_agg  = out;                       // 64*768
    float* out_pred = out + 49152;               // 64*256*768
    float* out_mask = out + 12632064;            // 64*256
    float* out_emb  = out + 12648448;            // 64*256*768

    float *h, *q, *k, *v, *o, *t, *f;
    cudaGetSymbolAddress((void**)&h, g_h);
    cudaGetSymbolAddress((void**)&q, g_q);
    cudaGetSymbolAddress((void**)&k, g_k);
    cudaGetSymbolAddress((void**)&v, g_v);
    cudaGetSymbolAddress((void**)&o, g_o);
    cudaGetSymbolAddress((void**)&t, g_t);
    cudaGetSymbolAddress((void**)&f, g_f);

    // conv (stride == kernel => pure GEMM), writes embeddings output directly
    run_gemm(inputs, conv_w, conv_b, out_emb, BSR, D_, 512, false);

    // build h (mask/shuffle/pos-emb/agg token) + mask_pos output
    assemble_kernel<<<ROWS, 256>>>(out_emb, randomness, perm, mask_tok, agg_tok,
                                   pos_emb, h, out_mask);

    const int SMEM_ATTN = (64 * SEQ + SEQ * 64 + 8 * SEQ + 8 * 64) * (int)sizeof(float);
    cudaFuncSetAttribute(attn_kernel, cudaFuncAttributeMaxDynamicSharedMemorySize, SMEM_ATTN);

    for (int l = 0; l < 2; l++) {
        size_t wOff = (size_t)l * D_ * D_;
        run_gemm(h, wq + wOff, bq + l * D_, q, ROWS, D_, D_, false);
        run_gemm(h, wk + wOff, bk + l * D_, k, ROWS, D_, D_, false);
        run_gemm(h, wv + wOff, bv + l * D_, v, ROWS, D_, D_, false);

        attn_kernel<<<dim3(HEADS, B_), 256, SMEM_ATTN>>>(q, k, v, o);

        run_gemm(o, wo + wOff, bo + l * D_, t, ROWS, D_, D_, false);
        add_ln_kernel<<<ROWS, 256>>>(h, t, ln1g + l * D_, ln1b + l * D_, h);

        run_gemm(h, w1 + (size_t)l * D_ * F_, b1 + l * F_, f, ROWS, F_, D_, true);
        run_gemm(f, w2 + (size_t)l * F_ * D_, b2 + l * D_, t, ROWS, D_, F_, false);
        add_ln_kernel<<<ROWS, 256>>>(h, t, ln2g + l * D_, ln2b + l * D_, h);
    }

    int total = ROWS * D_;
    writeout_kernel<<<(total + 255) / 256, 256>>>(h, out_agg, out_pred);
}

// round 3
// speedup vs baseline: 1.9552x; 1.0787x over previous
#include <cuda_runtime.h>
#include <math.h>
#include <stdint.h>

#define B_    64
#define SEQ   257          // S+1 rows per batch in h
#define S_    256
#define D_    768
#define F_    3072
#define HEADS 12
#define DKH   64
#define ROWS  (B_*SEQ)     // 16448
#define BSR   (B_*S_)      // 16384

// ---------------- scratch (static device globals; no allocation) ----------------
__device__ float g_h[(size_t)ROWS*D_];
__device__ float g_q[(size_t)ROWS*D_];
__device__ float g_k[(size_t)ROWS*D_];
__device__ float g_v[(size_t)ROWS*D_];
__device__ float g_o[(size_t)ROWS*D_];
__device__ float g_t[(size_t)ROWS*D_];
__device__ float g_f[(size_t)ROWS*F_];

__device__ __forceinline__ float gelu_f(float x) {
    float x3 = x * x * x;
    float t = tanhf(0.7978845608028654f * (x + 0.044715f * x3));
    return 0.5f * x * (1.0f + t);
}

__device__ __forceinline__ uint32_t f2tf(float x) {
    uint32_t u;
    asm("cvt.rna.tf32.f32 %0, %1;" : "=r"(u) : "f"(x));
    return u;
}

// ---------------- TF32 tensor-core GEMM, fragment-packed smem ----------------
// C = A(MxK,row) @ B(KxN,row) + bias, optional GELU.
// 128x128 block tile, BK=16, 256 threads (8 warps as 2x4), warp tile 64x32.
// A smem is stored in mma-fragment quads: one LDS.128 loads a full A fragment.
// B smem padded to 136 floats/row -> all fragment LDS.32 are conflict-free.
template<int ACT>
__global__ void __launch_bounds__(256, 2)
tgemm_kernel(const float* __restrict__ A, const float* __restrict__ Bm,
             const float* __restrict__ bias, float* __restrict__ C,
             int M, int N, int K)
{
    // A: [buf][kk(2)][mb(8)][p(32)] quads of 4 tf32 words
    __shared__ __align__(16) uint32_t As[2][2048];
    __shared__ __align__(16) uint32_t Bs[2][16][136];

    const int tid  = threadIdx.x;
    const int bm   = blockIdx.y * 128;
    const int bn   = blockIdx.x * 128;
    const int wid  = tid >> 5;
    const int lane = tid & 31;
    const int wm   = (wid & 1) * 64;      // warp m offset
    const int wn   = (wid >> 1) * 32;     // warp n offset
    const int g    = lane >> 2;           // groupID
    const int tig  = lane & 3;            // thread in group

    float acc[4][4][4];
#pragma unroll
    for (int i = 0; i < 4; i++)
#pragma unroll
        for (int j = 0; j < 4; j++)
#pragma unroll
            for (int c = 0; c < 4; c++) acc[i][j][c] = 0.f;

    // ---- A gather assignment: this thread owns quads (kk=0,1) at (mb, p) ----
    const int p   = tid & 31;
    const int mb  = (tid >> 5) & 7;
    const int gA  = p >> 2;
    const int tA  = p & 3;
    const int mlo = mb * 16 + gA;
    const int mhi = mlo + 8;
    const bool v0 = (bm + mlo) < M;
    const bool v1 = (bm + mhi) < M;
    const float* Alo = A + (size_t)(v0 ? (bm + mlo) : 0) * K;
    const float* Ahi = A + (size_t)(v1 ? (bm + mhi) : 0) * K;
    const int aoff0 = ((0 * 8 + mb) * 32 + p) * 4;
    const int aoff1 = ((1 * 8 + mb) * 32 + p) * 4;

    // ---- B staging: 2 float4 per thread, rows bk/bk+8, cols bc..bc+3 ----
    const int bk = tid >> 5;
    const int bc = lane << 2;
    const float* Bp0 = Bm + (size_t)bk       * N + bn + bc;
    const float* Bp1 = Bm + (size_t)(bk + 8) * N + bn + bc;

    const int nk = K / 16;

    // ---- prologue: tile 0 ----
    {
#pragma unroll
        for (int kk = 0; kk < 2; kk++) {
            const int kl = kk * 8 + tA;
            float x00 = v0 ? Alo[kl]     : 0.f;
            float x01 = v0 ? Alo[kl + 4] : 0.f;
            float x10 = v1 ? Ahi[kl]     : 0.f;
            float x11 = v1 ? Ahi[kl + 4] : 0.f;
            uint32_t* dst = &As[0][kk ? aoff1 : aoff0];
            dst[0] = f2tf(x00); dst[1] = f2tf(x10);
            dst[2] = f2tf(x01); dst[3] = f2tf(x11);
        }
        float4 b0 = *(const float4*)Bp0;
        float4 b1 = *(const float4*)Bp1;
        *(uint4*)&Bs[0][bk][bc]     = make_uint4(f2tf(b0.x), f2tf(b0.y), f2tf(b0.z), f2tf(b0.w));
        *(uint4*)&Bs[0][bk + 8][bc] = make_uint4(f2tf(b1.x), f2tf(b1.y), f2tf(b1.z), f2tf(b1.w));
    }
    __syncthreads();

    for (int kt = 0; kt < nk; kt++) {
        const int cur = kt & 1;
        const bool have_next = (kt + 1 < nk);

        // prefetch next tile into registers
        float na[2][4];
        float4 nb0, nb1;
        if (have_next) {
            const int off = (kt + 1) * 16;
#pragma unroll
            for (int kk = 0; kk < 2; kk++) {
                const int kl = off + kk * 8 + tA;
                na[kk][0] = v0 ? Alo[kl]     : 0.f;
                na[kk][1] = v1 ? Ahi[kl]     : 0.f;
                na[kk][2] = v0 ? Alo[kl + 4] : 0.f;
                na[kk][3] = v1 ? Ahi[kl + 4] : 0.f;
            }
            nb0 = *(const float4*)(Bp0 + (size_t)off * N);
            nb1 = *(const float4*)(Bp1 + (size_t)off * N);
        }

        // compute on current buffer
#pragma unroll
        for (int kk = 0; kk < 2; kk++) {
            uint4 af[4];
#pragma unroll
            for (int i = 0; i < 4; i++) {
                const int mbi = wm / 16 + i;   // wrow*4 + i
                af[i] = *(const uint4*)&As[cur][((kk * 8 + mbi) * 32 + lane) * 4];
            }
            const uint32_t* brow0 = &Bs[cur][kk * 8 + tig][0];
            const uint32_t* brow1 = &Bs[cur][kk * 8 + tig + 4][0];
            uint32_t bf0[4], bf1[4];
#pragma unroll
            for (int j = 0; j < 4; j++) {
                const int n0 = wn + j * 8 + g;
                bf0[j] = brow0[n0];
                bf1[j] = brow1[n0];
            }
#pragma unroll
            for (int i = 0; i < 4; i++)
#pragma unroll
                for (int j = 0; j < 4; j++) {
                    asm volatile(
                        "mma.sync.aligned.m16n8k8.row.col.f32.tf32.tf32.f32 "
                        "{%0,%1,%2,%3}, {%4,%5,%6,%7}, {%8,%9}, {%0,%1,%2,%3};"
                        : "+f"(acc[i][j][0]), "+f"(acc[i][j][1]),
                          "+f"(acc[i][j][2]), "+f"(acc[i][j][3])
                        : "r"(af[i].x), "r"(af[i].y), "r"(af[i].z), "r"(af[i].w),
                          "r"(bf0[j]), "r"(bf1[j]));
                }
        }

        // stage next tile
        if (have_next) {
            const int nxt = cur ^ 1;
#pragma unroll
            for (int kk = 0; kk < 2; kk++) {
                uint32_t* dst = &As[nxt][kk ? aoff1 : aoff0];
                dst[0] = f2tf(na[kk][0]); dst[1] = f2tf(na[kk][1]);
                dst[2] = f2tf(na[kk][2]); dst[3] = f2tf(na[kk][3]);
            }
            *(uint4*)&Bs[nxt][bk][bc]     = make_uint4(f2tf(nb0.x), f2tf(nb0.y), f2tf(nb0.z), f2tf(nb0.w));
            *(uint4*)&Bs[nxt][bk + 8][bc] = make_uint4(f2tf(nb1.x), f2tf(nb1.y), f2tf(nb1.z), f2tf(nb1.w));
        }
        __syncthreads();
    }

    // ---- epilogue: bias (+GELU), float2 stores ----
#pragma unroll
    for (int i = 0; i < 4; i++) {
        const int r0 = bm + wm + i * 16 + g;
        const int r1 = r0 + 8;
#pragma unroll
        for (int j = 0; j < 4; j++) {
            const int col = bn + wn + j * 8 + 2 * tig;
            const float bv0 = bias[col];
            const float bv1 = bias[col + 1];
            float v0 = acc[i][j][0] + bv0;
            float v1 = acc[i][j][1] + bv1;
            float v2 = acc[i][j][2] + bv0;
            float v3 = acc[i][j][3] + bv1;
            if (ACT == 1) { v0 = gelu_f(v0); v1 = gelu_f(v1); v2 = gelu_f(v2); v3 = gelu_f(v3); }
            if (r0 < M) *(float2*)&C[(size_t)r0 * N + col] = make_float2(v0, v1);
            if (r1 < M) *(float2*)&C[(size_t)r1 * N + col] = make_float2(v2, v3);
        }
    }
}

// ---------------- assemble h: masking + shuffle gather + pos emb + agg token ----------------
__global__ void assemble_kernel(const float* __restrict__ x,
                                const float* __restrict__ rnd,
                                const int*   __restrict__ perm,
                                const float* __restrict__ mask_tok,
                                const float* __restrict__ agg_tok,
                                const float* __restrict__ pos_emb,
                                float* __restrict__ h,
                                float* __restrict__ mask_pos)
{
    int row = blockIdx.x;
    int b   = row / SEQ;
    int sp  = row - b * SEQ;
    int tid = threadIdx.x;
    float* hp = h + (size_t)row * D_;

    if (sp == 0) {
        hp[tid]       = agg_tok[tid];
        hp[tid + 256] = agg_tok[tid + 256];
        hp[tid + 512] = agg_tok[tid + 512];
        return;
    }
    int s = sp - 1;
    int i = b * S_ + s;
    float r0 = rnd[i * 3 + 0];
    float r1 = rnd[i * 3 + 1];
    float r2 = rnd[i * 3 + 2];
    bool  sel = (r0 <= 0.2f);
    float m  = (sel && r1 <= 0.8f) ? 1.f : 0.f;
    float rd = (sel && r1 > 0.8f && r2 <= 0.5f) ? 1.f : 0.f;
    if (tid == 0) mask_pos[i] = sel ? 1.f : 0.f;

    int pi = perm[i];
    const float* xp = x + (size_t)i  * D_;
    const float* sh = x + (size_t)pi * D_;
    const float* pe = pos_emb + (size_t)s * D_;
    float keep = 1.f - m - rd;

#pragma unroll
    for (int e = 0; e < 3; e++) {
        int d = tid + e * 256;
        hp[d] = xp[d] * keep + mask_tok[d] * m + sh[d] * rd + pe[d];
    }
}

// ---------------- attention: one block per (head, batch) ----------------
__global__ void __launch_bounds__(256)
attn_kernel(const float* __restrict__ Q, const float* __restrict__ K,
            const float* __restrict__ V, float* __restrict__ O)
{
    extern __shared__ float sm[];
    float* Kt    = sm;                         // 64*257
    float* Vs    = Kt + 64 * 257;              // 257*64
    float* probs = Vs + 257 * 64;              // 8*257
    float* qbuf  = probs + 8 * 257;            // 8*64

    int hh = blockIdx.x;
    int bb = blockIdx.y;
    int tid = threadIdx.x;
    const size_t base = ((size_t)bb * SEQ) * D_ + (size_t)hh * DKH;

    for (int idx = tid; idx < SEQ * DKH; idx += 256) {
        int k = idx >> 6;
        int d = idx & 63;
        float kv = K[base + (size_t)k * D_ + d];
        Kt[d * SEQ + k] = kv;
        Vs[idx] = V[base + (size_t)k * D_ + d];
    }
    __syncthreads();

    int w = tid >> 5, lane = tid & 31;
    float* qw = qbuf + w * 64;
    float* pw = probs + w * SEQ;

    for (int q = w; q < SEQ; q += 8) {
        const float* qp = Q + base + (size_t)q * D_;
        qw[lane]      = qp[lane];
        qw[lane + 32] = qp[lane + 32];
        __syncwarp();

        float s[9];
        float mx = -1e30f;
#pragma unroll
        for (int j = 0; j < 9; j++) {
            int k = lane + j * 32;
            float acc = -1e30f;
            if (k < SEQ) {
                acc = 0.f;
                for (int d = 0; d < 64; d++)
                    acc += qw[d] * Kt[d * SEQ + k];
                acc *= 0.125f;
                mx = fmaxf(mx, acc);
            }
            s[j] = acc;
        }
        for (int off = 16; off; off >>= 1)
            mx = fmaxf(mx, __shfl_xor_sync(0xffffffffu, mx, off));

        float sum = 0.f;
#pragma unroll
        for (int j = 0; j < 9; j++) {
            int k = lane + j * 32;
            float e = 0.f;
            if (k < SEQ) { e = expf(s[j] - mx); sum += e; }
            s[j] = e;
        }
        for (int off = 16; off; off >>= 1)
            sum += __shfl_xor_sync(0xffffffffu, sum, off);
        float inv = 1.f / sum;
#pragma unroll
        for (int j = 0; j < 9; j++) {
            int k = lane + j * 32;
            if (k < SEQ) pw[k] = s[j] * inv;
        }
        __syncwarp();

        float o0 = 0.f, o1 = 0.f;
        for (int k = 0; k < SEQ; k++) {
            float p = pw[k];
            float2 v2 = *(const float2*)&Vs[k * 64 + 2 * lane];
            o0 += p * v2.x;
            o1 += p * v2.y;
        }
        *(float2*)&O[base + (size_t)q * D_ + 2 * lane] = make_float2(o0, o1);
        __syncwarp();
    }
}

// ---------------- residual + LayerNorm ----------------
__global__ void add_ln_kernel(const float* __restrict__ H, const float* __restrict__ Dl,
                              const float* __restrict__ g, const float* __restrict__ be,
                              float* __restrict__ Out)
{
    int row = blockIdx.x, tid = threadIdx.x;
    const float* hp = H  + (size_t)row * D_;
    const float* dp = Dl + (size_t)row * D_;
    float v0 = hp[tid]       + dp[tid];
    float v1 = hp[tid + 256] + dp[tid + 256];
    float v2 = hp[tid + 512] + dp[tid + 512];

    __shared__ float red[8];
    __shared__ float s_mu, s_var;
    int lane = tid & 31, w = tid >> 5;

    float s = v0 + v1 + v2;
    for (int off = 16; off; off >>= 1) s += __shfl_xor_sync(0xffffffffu, s, off);
    if (lane == 0) red[w] = s;
    __syncthreads();
    if (tid == 0) {
        float t = 0.f;
        for (int i = 0; i < 8; i++) t += red[i];
        s_mu = t * (1.0f / 768.0f);
    }
    __syncthreads();
    float mu = s_mu;
    float d0 = v0 - mu, d1 = v1 - mu, d2 = v2 - mu;
    float qv = d0 * d0 + d1 * d1 + d2 * d2;
    for (int off = 16; off; off >>= 1) qv += __shfl_xor_sync(0xffffffffu, qv, off);
    if (lane == 0) red[w] = qv;
    __syncthreads();
    if (tid == 0) {
        float t = 0.f;
        for (int i = 0; i < 8; i++) t += red[i];
        s_var = t * (1.0f / 768.0f);
    }
    __syncthreads();
    float rs = rsqrtf(s_var + 1e-6f);

    float* op = Out + (size_t)row * D_;
    op[tid]       = d0 * rs * g[tid]       + be[tid];
    op[tid + 256] = d1 * rs * g[tid + 256] + be[tid + 256];
    op[tid + 512] = d2 * rs * g[tid + 512] + be[tid + 512];
}

// ---------------- scatter h -> aggregated + predictions ----------------
__global__ void writeout_kernel(const float* __restrict__ h,
                                float* __restrict__ agg, float* __restrict__ pred)
{
    size_t idx = (size_t)blockIdx.x * 256 + threadIdx.x;
    if (idx >= (size_t)ROWS * D_) return;
    int row = (int)(idx / D_);
    int d   = (int)(idx - (size_t)row * D_);
    int b   = row / SEQ;
    int sp  = row - b * SEQ;
    float val = h[idx];
    if (sp == 0) agg[(size_t)b * D_ + d] = val;
    else pred[((size_t)(b * S_ + sp - 1)) * D_ + d] = val;
}

// ---------------- host ----------------
static inline void run_gemm(const float* A, const float* Bm, const float* bias,
                            float* C, int M, int N, int K, bool gelu)
{
    dim3 grid(N / 128, (M + 127) / 128);
    if (gelu) tgemm_kernel<1><<<grid, 256>>>(A, Bm, bias, C, M, N, K);
    else      tgemm_kernel<0><<<grid, 256>>>(A, Bm, bias, C, M, N, K);
}

extern "C" void kernel_launch(void* const* d_in, const int* in_sizes, int n_in,
                              void* d_out, int out_size)
{
    const float* inputs     = (const float*)d_in[0];
    const float* randomness = (const float*)d_in[1];
    const int*   perm       = (const int*)  d_in[2];
    const float* conv_w     = (const float*)d_in[3];
    const float* conv_b     = (const float*)d_in[4];
    const float* pos_emb    = (const float*)d_in[5];
    const float* mask_tok   = (const float*)d_in[6];
    const float* agg_tok    = (const float*)d_in[7];
    const float* wq  = (const float*)d_in[8];
    const float* bq  = (const float*)d_in[9];
    const float* wk  = (const float*)d_in[10];
    const float* bk  = (const float*)d_in[11];
    const float* wv  = (const float*)d_in[12];
    const float* bv  = (const float*)d_in[13];
    const float* wo  = (const float*)d_in[14];
    const float* bo  = (const float*)d_in[15];
    const float* ln1g = (const float*)d_in[16];
    const float* ln1b = (const float*)d_in[17];
    const float* w1  = (const float*)d_in[18];
    const float* b1  = (const float*)d_in[19];
    const float* w2  = (const float*)d_in[20];
    const float* b2  = (const float*)d_in[21];
    const float* ln2g = (const float*)d_in[22];
    const float* ln2b = (const float*)d_in[23];

    float* out      = (float*)d_out;
    float* out_agg  = out;                       // 64*768
    float* out_pred = out + 49152;               // 64*256*768
    float* out_mask = out + 12632064;            // 64*256
    float* out_emb  = out + 12648448;            // 64*256*768

    float *h, *q, *k, *v, *o, *t, *f;
    cudaGetSymbolAddress((void**)&h, g_h);
    cudaGetSymbolAddress((void**)&q, g_q);
    cudaGetSymbolAddress((void**)&k, g_k);
    cudaGetSymbolAddress((void**)&v, g_v);
    cudaGetSymbolAddress((void**)&o, g_o);
    cudaGetSymbolAddress((void**)&t, g_t);
    cudaGetSymbolAddress((void**)&f, g_f);

    // conv (stride == kernel => pure GEMM), writes embeddings output directly
    run_gemm(inputs, conv_w, conv_b, out_emb, BSR, D_, 512, false);

    // build h (mask/shuffle/pos-emb/agg token) + mask_pos output
    assemble_kernel<<<ROWS, 256>>>(out_emb, randomness, perm, mask_tok, agg_tok,
                                   pos_emb, h, out_mask);

    const int SMEM_ATTN = (64 * SEQ + SEQ * 64 + 8 * SEQ + 8 * 64) * (int)sizeof(float);
    cudaFuncSetAttribute(attn_kernel, cudaFuncAttributeMaxDynamicSharedMemorySize, SMEM_ATTN);

    for (int l = 0; l < 2; l++) {
        size_t wOff = (size_t)l * D_ * D_;
        run_gemm(h, wq + wOff, bq + l * D_, q, ROWS, D_, D_, false);
        run_gemm(h, wk + wOff, bk + l * D_, k, ROWS, D_, D_, false);
        run_gemm(h, wv + wOff, bv + l * D_, v, ROWS, D_, D_, false);

        attn_kernel<<<dim3(HEADS, B_), 256, SMEM_ATTN>>>(q, k, v, o);

        run_gemm(o, wo + wOff, bo + l * D_, t, ROWS, D_, D_, false);
        add_ln_kernel<<<ROWS, 256>>>(h, t, ln1g + l * D_, ln1b + l * D_, h);

        run_gemm(h, w1 + (size_t)l * D_ * F_, b1 + l * F_, f, ROWS, F_, D_, true);
        run_gemm(f, w2 + (size_t)l * F_ * D_, b2 + l * D_, t, ROWS, D_, F_, false);
        add_ln_kernel<<<ROWS, 256>>>(h, t, ln2g + l * D_, ln2b + l * D_, h);
    }

    int total = ROWS * D_;
    writeout_kernel<<<(total + 255) / 256, 256>>>(h, out_agg, out_pred);
}

// round 5
// speedup vs baseline: 2.0350x; 1.0408x over previous
#include <cuda_runtime.h>
#include <math.h>
#include <stdint.h>

#define B_    64
#define SEQ   257          // S+1 rows per batch in h
#define S_    256
#define D_    768
#define F_    3072
#define HEADS 12
#define DKH   64
#define ROWS  (B_*SEQ)     // 16448
#define BSR   (B_*S_)      // 16384

// ---------------- scratch (static device globals; no allocation) ----------------
__device__ float g_h[(size_t)ROWS*D_];
__device__ float g_q[(size_t)ROWS*D_];
__device__ float g_k[(size_t)ROWS*D_];
__device__ float g_v[(size_t)ROWS*D_];
__device__ float g_o[(size_t)ROWS*D_];
__device__ float g_t[(size_t)ROWS*D_];
__device__ float g_f[(size_t)ROWS*F_];

__device__ __forceinline__ float gelu_f(float x) {
    float x3 = x * x * x;
    float t = tanhf(0.7978845608028654f * (x + 0.044715f * x3));
    return 0.5f * x * (1.0f + t);
}

__device__ __forceinline__ uint32_t f2tf(float x) {
    uint32_t u;
    asm("cvt.rna.tf32.f32 %0, %1;" : "=r"(u) : "f"(x));
    return u;
}

// ---------------- TF32 tensor-core GEMM, 128x256 block, 64x64 warp tiles ----------------
// C = A(MxK,row) @ B(KxN,row) + bias, optional GELU. BK=16, 256 threads (8 warps 2x4).
// A smem fragment-packed (one LDS.128 = one full mma A fragment).
// B smem rows padded to 264 floats: fragment LDS.32 hits 32 distinct banks.
template<int ACT>
__global__ void __launch_bounds__(256, 1)
tgemm_kernel(const float* __restrict__ A, const float* __restrict__ Bm,
             const float* __restrict__ bias, float* __restrict__ C,
             int M, int N, int K)
{
    extern __shared__ char dsm[];
    uint32_t (*As)[2048]    = (uint32_t (*)[2048])dsm;                 // [2][2048] quads
    uint32_t (*Bs)[16][264] = (uint32_t (*)[16][264])(dsm + 16384);    // [2][16][264]

    const int tid  = threadIdx.x;
    const int bm   = blockIdx.y * 128;
    const int bn   = blockIdx.x * 256;
    const int wid  = tid >> 5;
    const int lane = tid & 31;
    const int wm   = (wid & 1) * 64;      // warp m offset
    const int wn   = (wid >> 1) * 64;     // warp n offset
    const int g    = lane >> 2;           // groupID
    const int tig  = lane & 3;            // thread in group

    float acc[4][8][4];
#pragma unroll
    for (int i = 0; i < 4; i++)
#pragma unroll
        for (int j = 0; j < 8; j++)
#pragma unroll
            for (int c = 0; c < 4; c++) acc[i][j][c] = 0.f;

    // ---- A gather: thread owns quads (kk=0,1) at (mb, p) ----
    const int p   = tid & 31;
    const int mb  = (tid >> 5) & 7;
    const int gA  = p >> 2;
    const int tA  = p & 3;
    const int mlo = mb * 16 + gA;
    const int mhi = mlo + 8;
    const bool v0 = (bm + mlo) < M;
    const bool v1 = (bm + mhi) < M;
    const float* Alo = A + (size_t)(v0 ? (bm + mlo) : 0) * K;
    const float* Ahi = A + (size_t)(v1 ? (bm + mhi) : 0) * K;
    const int aoff0 = ((0 * 8 + mb) * 32 + p) * 4;
    const int aoff1 = ((1 * 8 + mb) * 32 + p) * 4;

    // ---- B staging: 4 float4 per thread; rows br+4m, cols bc4..bc4+3 ----
    const int br  = tid >> 6;             // 0..3
    const int bc4 = (tid & 63) << 2;      // 0..252
    const float* Bbase = Bm + bn + bc4;

    const int nk = K / 16;

    // ---- prologue: stage tile 0 ----
    {
#pragma unroll
        for (int kk = 0; kk < 2; kk++) {
            const int kl = kk * 8 + tA;
            float x00 = v0 ? Alo[kl]     : 0.f;
            float x01 = v0 ? Alo[kl + 4] : 0.f;
            float x10 = v1 ? Ahi[kl]     : 0.f;
            float x11 = v1 ? Ahi[kl + 4] : 0.f;
            uint32_t* dst = &As[0][kk ? aoff1 : aoff0];
            dst[0] = f2tf(x00); dst[1] = f2tf(x10);
            dst[2] = f2tf(x01); dst[3] = f2tf(x11);
        }
#pragma unroll
        for (int m = 0; m < 4; m++) {
            const int row = br + 4 * m;
            float4 b = *(const float4*)(Bbase + (size_t)row * N);
            *(uint4*)&Bs[0][row][bc4] = make_uint4(f2tf(b.x), f2tf(b.y), f2tf(b.z), f2tf(b.w));
        }
    }
    __syncthreads();

    for (int kt = 0; kt < nk; kt++) {
        const int cur = kt & 1;
        const bool have_next = (kt + 1 < nk);

        // prefetch next tile into registers
        float na[2][4];
        float4 nb[4];
        if (have_next) {
            const int off = (kt + 1) * 16;
#pragma unroll
            for (int kk = 0; kk < 2; kk++) {
                const int kl = off + kk * 8 + tA;
                na[kk][0] = v0 ? Alo[kl]     : 0.f;
                na[kk][1] = v1 ? Ahi[kl]     : 0.f;
                na[kk][2] = v0 ? Alo[kl + 4] : 0.f;
                na[kk][3] = v1 ? Ahi[kl + 4] : 0.f;
            }
#pragma unroll
            for (int m = 0; m < 4; m++)
                nb[m] = *(const float4*)(Bbase + (size_t)(off + br + 4 * m) * N);
        }

        // compute on current buffer
#pragma unroll
        for (int kk = 0; kk < 2; kk++) {
            const uint32_t* brow0 = &Bs[cur][kk * 8 + tig][0];
            const uint32_t* brow1 = &Bs[cur][kk * 8 + tig + 4][0];
            uint32_t bf0[8], bf1[8];
#pragma unroll
            for (int j = 0; j < 8; j++) {
                const int n0 = wn + j * 8 + g;
                bf0[j] = brow0[n0];
                bf1[j] = brow1[n0];
            }
#pragma unroll
            for (int i = 0; i < 4; i++) {
                const int mbi = (wm >> 4) + i;
                uint4 af = *(const uint4*)&As[cur][((kk * 8 + mbi) * 32 + lane) * 4];
#pragma unroll
                for (int j = 0; j < 8; j++) {
                    asm volatile(
                        "mma.sync.aligned.m16n8k8.row.col.f32.tf32.tf32.f32 "
                        "{%0,%1,%2,%3}, {%4,%5,%6,%7}, {%8,%9}, {%0,%1,%2,%3};"
                        : "+f"(acc[i][j][0]), "+f"(acc[i][j][1]),
                          "+f"(acc[i][j][2]), "+f"(acc[i][j][3])
                        : "r"(af.x), "r"(af.y), "r"(af.z), "r"(af.w),
                          "r"(bf0[j]), "r"(bf1[j]));
                }
            }
        }

        // stage next tile
        if (have_next) {
            const int nxt = cur ^ 1;
#pragma unroll
            for (int kk = 0; kk < 2; kk++) {
                uint32_t* dst = &As[nxt][kk ? aoff1 : aoff0];
                dst[0] = f2tf(na[kk][0]); dst[1] = f2tf(na[kk][1]);
                dst[2] = f2tf(na[kk][2]); dst[3] = f2tf(na[kk][3]);
            }
#pragma unroll
            for (int m = 0; m < 4; m++) {
                const int row = br + 4 * m;
                *(uint4*)&Bs[nxt][row][bc4] =
                    make_uint4(f2tf(nb[m].x), f2tf(nb[m].y), f2tf(nb[m].z), f2tf(nb[m].w));
            }
        }
        __syncthreads();
    }

    // ---- epilogue: bias (+GELU), float2 stores ----
#pragma unroll
    for (int i = 0; i < 4; i++) {
        const int r0 = bm + wm + i * 16 + g;
        const int r1 = r0 + 8;
#pragma unroll
        for (int j = 0; j < 8; j++) {
            const int col = bn + wn + j * 8 + 2 * tig;
            const float bv0 = bias[col];
            const float bv1 = bias[col + 1];
            float v0a = acc[i][j][0] + bv0;
            float v1a = acc[i][j][1] + bv1;
            float v2a = acc[i][j][2] + bv0;
            float v3a = acc[i][j][3] + bv1;
            if (ACT == 1) { v0a = gelu_f(v0a); v1a = gelu_f(v1a); v2a = gelu_f(v2a); v3a = gelu_f(v3a); }
            if (r0 < M) *(float2*)&C[(size_t)r0 * N + col] = make_float2(v0a, v1a);
            if (r1 < M) *(float2*)&C[(size_t)r1 * N + col] = make_float2(v2a, v3a);
        }
    }
}

#define GEMM_SMEM (16384 + 2*16*264*4)

// ---------------- assemble h: masking + shuffle gather + pos emb + agg token ----------------
__global__ void assemble_kernel(const float* __restrict__ x,
                                const float* __restrict__ rnd,
                                const int*   __restrict__ perm,
                                const float* __restrict__ mask_tok,
                                const float* __restrict__ agg_tok,
                                const float* __restrict__ pos_emb,
                                float* __restrict__ h,
                                float* __restrict__ mask_pos)
{
    int row = blockIdx.x;
    int b   = row / SEQ;
    int sp  = row - b * SEQ;
    int tid = threadIdx.x;
    float* hp = h + (size_t)row * D_;

    if (sp == 0) {
        hp[tid]       = agg_tok[tid];
        hp[tid + 256] = agg_tok[tid + 256];
        hp[tid + 512] = agg_tok[tid + 512];
        return;
    }
    int s = sp - 1;
    int i = b * S_ + s;
    float r0 = rnd[i * 3 + 0];
    float r1 = rnd[i * 3 + 1];
    float r2 = rnd[i * 3 + 2];
    bool  sel = (r0 <= 0.2f);
    float m  = (sel && r1 <= 0.8f) ? 1.f : 0.f;
    float rd = (sel && r1 > 0.8f && r2 <= 0.5f) ? 1.f : 0.f;
    if (tid == 0) mask_pos[i] = sel ? 1.f : 0.f;

    int pi = perm[i];
    const float* xp = x + (size_t)i  * D_;
    const float* sh = x + (size_t)pi * D_;
    const float* pe = pos_emb + (size_t)s * D_;
    float keep = 1.f - m - rd;

#pragma unroll
    for (int e = 0; e < 3; e++) {
        int d = tid + e * 256;
        hp[d] = xp[d] * keep + mask_tok[d] * m + sh[d] * rd + pe[d];
    }
}

// ---------------- attention: one block per (head, batch) ----------------
__global__ void __launch_bounds__(256)
attn_kernel(const float* __restrict__ Q, const float* __restrict__ K,
            const float* __restrict__ V, float* __restrict__ O)
{
    extern __shared__ float sm[];
    float* Kt    = sm;                         // 64*257
    float* Vs    = Kt + 64 * 257;              // 257*64
    float* probs = Vs + 257 * 64;              // 8*257
    float* qbuf  = probs + 8 * 257;            // 8*64

    int hh = blockIdx.x;
    int bb = blockIdx.y;
    int tid = threadIdx.x;
    const size_t base = ((size_t)bb * SEQ) * D_ + (size_t)hh * DKH;

    for (int idx = tid; idx < SEQ * DKH; idx += 256) {
        int k = idx >> 6;
        int d = idx & 63;
        float kv = K[base + (size_t)k * D_ + d];
        Kt[d * SEQ + k] = kv;
        Vs[idx] = V[base + (size_t)k * D_ + d];
    }
    __syncthreads();

    int w = tid >> 5, lane = tid & 31;
    float* qw = qbuf + w * 64;
    float* pw = probs + w * SEQ;

    for (int q = w; q < SEQ; q += 8) {
        const float* qp = Q + base + (size_t)q * D_;
        qw[lane]      = qp[lane];
        qw[lane + 32] = qp[lane + 32];
        __syncwarp();

        float s[9];
#pragma unroll
        for (int j = 0; j < 9; j++) s[j] = 0.f;

        // d-outer / j-inner: qw[d] is one LDS per d (was 9)
#pragma unroll 4
        for (int d = 0; d < 64; d++) {
            float qv = qw[d];
            const float* kr = &Kt[d * SEQ + lane];
#pragma unroll
            for (int j = 0; j < 9; j++)
                s[j] += qv * kr[j * 32];   // j=8 lanes>0 read spill (masked below)
        }

        float mx = -1e30f;
#pragma unroll
        for (int j = 0; j < 9; j++) {
            int k = lane + j * 32;
            s[j] = (k < SEQ) ? s[j] * 0.125f : -1e30f;
            mx = fmaxf(mx, s[j]);
        }
        for (int off = 16; off; off >>= 1)
            mx = fmaxf(mx, __shfl_xor_sync(0xffffffffu, mx, off));

        float sum = 0.f;
#pragma unroll
        for (int j = 0; j < 9; j++) {
            float e = __expf(s[j] - mx);
            sum += e;
            s[j] = e;
        }
        for (int off = 16; off; off >>= 1)
            sum += __shfl_xor_sync(0xffffffffu, sum, off);
        float inv = 1.f / sum;
#pragma unroll
        for (int j = 0; j < 9; j++) {
            int k = lane + j * 32;
            if (k < SEQ) pw[k] = s[j] * inv;
        }
        __syncwarp();

        float o0 = 0.f, o1 = 0.f;
#pragma unroll 4
        for (int k = 0; k < SEQ; k++) {
            float pv = pw[k];
            float2 v2 = *(const float2*)&Vs[k * 64 + 2 * lane];
            o0 += pv * v2.x;
            o1 += pv * v2.y;
        }
        *(float2*)&O[base + (size_t)q * D_ + 2 * lane] = make_float2(o0, o1);
        __syncwarp();
    }
}

// ---------------- residual + LayerNorm ----------------
__global__ void add_ln_kernel(const float* __restrict__ H, const float* __restrict__ Dl,
                              const float* __restrict__ g, const float* __restrict__ be,
                              float* __restrict__ Out)
{
    int row = blockIdx.x, tid = threadIdx.x;
    const float* hp = H  + (size_t)row * D_;
    const float* dp = Dl + (size_t)row * D_;
    float v0 = hp[tid]       + dp[tid];
    float v1 = hp[tid + 256] + dp[tid + 256];
    float v2 = hp[tid + 512] + dp[tid + 512];

    __shared__ float red[8];
    __shared__ float s_mu, s_var;
    int lane = tid & 31, w = tid >> 5;

    float s = v0 + v1 + v2;
    for (int off = 16; off; off >>= 1) s += __shfl_xor_sync(0xffffffffu, s, off);
    if (lane == 0) red[w] = s;
    __syncthreads();
    if (tid == 0) {
        float t = 0.f;
        for (int i = 0; i < 8; i++) t += red[i];
        s_mu = t * (1.0f / 768.0f);
    }
    __syncthreads();
    float mu = s_mu;
    float d0 = v0 - mu, d1 = v1 - mu, d2 = v2 - mu;
    float qv = d0 * d0 + d1 * d1 + d2 * d2;
    for (int off = 16; off; off >>= 1) qv += __shfl_xor_sync(0xffffffffu, qv, off);
    if (lane == 0) red[w] = qv;
    __syncthreads();
    if (tid == 0) {
        float t = 0.f;
        for (int i = 0; i < 8; i++) t += red[i];
        s_var = t * (1.0f / 768.0f);
    }
    __syncthreads();
    float rs = rsqrtf(s_var + 1e-6f);

    float* op = Out + (size_t)row * D_;
    op[tid]       = d0 * rs * g[tid]       + be[tid];
    op[tid + 256] = d1 * rs * g[tid + 256] + be[tid + 256];
    op[tid + 512] = d2 * rs * g[tid + 512] + be[tid + 512];
}

// ---------------- scatter h -> aggregated + predictions ----------------
__global__ void writeout_kernel(const float* __restrict__ h,
                                float* __restrict__ agg, float* __restrict__ pred)
{
    size_t idx = (size_t)blockIdx.x * 256 + threadIdx.x;
    if (idx >= (size_t)ROWS * D_) return;
    int row = (int)(idx / D_);
    int d   = (int)(idx - (size_t)row * D_);
    int b   = row / SEQ;
    int sp  = row - b * SEQ;
    float val = h[idx];
    if (sp == 0) agg[(size_t)b * D_ + d] = val;
    else pred[((size_t)(b * S_ + sp - 1)) * D_ + d] = val;
}

// ---------------- host ----------------
static inline void run_gemm(const float* A, const float* Bm, const float* bias,
                            float* C, int M, int N, int K, bool gelu)
{
    dim3 grid(N / 256, (M + 127) / 128);
    if (gelu) tgemm_kernel<1><<<grid, 256, GEMM_SMEM>>>(A, Bm, bias, C, M, N, K);
    else      tgemm_kernel<0><<<grid, 256, GEMM_SMEM>>>(A, Bm, bias, C, M, N, K);
}

extern "C" void kernel_launch(void* const* d_in, const int* in_sizes, int n_in,
                              void* d_out, int out_size)
{
    const float* inputs     = (const float*)d_in[0];
    const float* randomness = (const float*)d_in[1];
    const int*   perm       = (const int*)  d_in[2];
    const float* conv_w     = (const float*)d_in[3];
    const float* conv_b     = (const float*)d_in[4];
    const float* pos_emb    = (const float*)d_in[5];
    const float* mask_tok   = (const float*)d_in[6];
    const float* agg_tok    = (const float*)d_in[7];
    const float* wq  = (const float*)d_in[8];
    const float* bq  = (const float*)d_in[9];
    const float* wk  = (const float*)d_in[10];
    const float* bk  = (const float*)d_in[11];
    const float* wv  = (const float*)d_in[12];
    const float* bv  = (const float*)d_in[13];
    const float* wo  = (const float*)d_in[14];
    const float* bo  = (const float*)d_in[15];
    const float* ln1g = (const float*)d_in[16];
    const float* ln1b = (const float*)d_in[17];
    const float* w1  = (const float*)d_in[18];
    const float* b1  = (const float*)d_in[19];
    const float* w2  = (const float*)d_in[20];
    const float* b2  = (const float*)d_in[21];
    const float* ln2g = (const float*)d_in[22];
    const float* ln2b = (const float*)d_in[23];

    float* out      = (float*)d_out;
    float* out_agg  = out;                       // 64*768
    float* out_pred = out + 49152;               // 64*256*768
    float* out_mask = out + 12632064;            // 64*256
    float* out_emb  = out + 12648448;            // 64*256*768

    float *h, *q, *k, *v, *o, *t, *f;
    cudaGetSymbolAddress((void**)&h, g_h);
    cudaGetSymbolAddress((void**)&q, g_q);
    cudaGetSymbolAddress((void**)&k, g_k);
    cudaGetSymbolAddress((void**)&v, g_v);
    cudaGetSymbolAddress((void**)&o, g_o);
    cudaGetSymbolAddress((void**)&t, g_t);
    cudaGetSymbolAddress((void**)&f, g_f);

    cudaFuncSetAttribute(tgemm_kernel<0>, cudaFuncAttributeMaxDynamicSharedMemorySize, GEMM_SMEM);
    cudaFuncSetAttribute(tgemm_kernel<1>, cudaFuncAttributeMaxDynamicSharedMemorySize, GEMM_SMEM);

    // conv (stride == kernel => pure GEMM), writes embeddings output directly
    run_gemm(inputs, conv_w, conv_b, out_emb, BSR, D_, 512, false);

    // build h (mask/shuffle/pos-emb/agg token) + mask_pos output
    assemble_kernel<<<ROWS, 256>>>(out_emb, randomness, perm, mask_tok, agg_tok,
                                   pos_emb, h, out_mask);

    const int SMEM_ATTN = (64 * SEQ + SEQ * 64 + 8 * SEQ + 8 * 64) * (int)sizeof(float);
    cudaFuncSetAttribute(attn_kernel, cudaFuncAttributeMaxDynamicSharedMemorySize, SMEM_ATTN);

    for (int l = 0; l < 2; l++) {
        size_t wOff = (size_t)l * D_ * D_;
        run_gemm(h, wq + wOff, bq + l * D_, q, ROWS, D_, D_, false);
        run_gemm(h, wk + wOff, bk + l * D_, k, ROWS, D_, D_, false);
        run_gemm(h, wv + wOff, bv + l * D_, v, ROWS, D_, D_, false);

        attn_kernel<<<dim3(HEADS, B_), 256, SMEM_ATTN>>>(q, k, v, o);

        run_gemm(o, wo + wOff, bo + l * D_, t, ROWS, D_, D_, false);
        add_ln_kernel<<<ROWS, 256>>>(h, t, ln1g + l * D_, ln1b + l * D_, h);

        run_gemm(h, w1 + (size_t)l * D_ * F_, b1 + l * F_, f, ROWS, F_, D_, true);
        run_gemm(f, w2 + (size_t)l * F_ * D_, b2 + l * D_, t, ROWS, D_, F_, false);
        add_ln_kernel<<<ROWS, 256>>>(h, t, ln2g + l * D_, ln2b + l * D_, h);
    }

    int total = ROWS * D_;
    writeout_kernel<<<(total + 255) / 256, 256>>>(h, out_agg, out_pred);
}

// round 6
// speedup vs baseline: 2.2409x; 1.1012x over previous
#include <cuda_runtime.h>
#include <math.h>
#include <stdint.h>

#define B_    64
#define SEQ   257
#define S_    256
#define D_    768
#define F_    3072
#define HEADS 12
#define DKH   64
#define ROWS  (B_*SEQ)     // 16448
#define BSR   (B_*S_)      // 16384

// ---------------- scratch ----------------
__device__ float g_h[(size_t)ROWS*D_];
__device__ float g_q[(size_t)ROWS*D_];
__device__ float g_k[(size_t)ROWS*D_];
__device__ float g_v[(size_t)ROWS*D_];
__device__ float g_o[(size_t)ROWS*D_];
__device__ float g_t[(size_t)ROWS*D_];
__device__ float g_f[(size_t)ROWS*F_];
__device__ float g_wr[14155776];   // tf32-RNA pre-rounded weights

// region offsets inside g_wr
#define RQ_OFF 0
#define RK_OFF 1179648
#define RV_OFF 2359296
#define RO_OFF 3538944
#define R1_OFF 4718592
#define R2_OFF 9437184

__device__ __forceinline__ float gelu_f(float x) {
    float x3 = x * x * x;
    float t = tanhf(0.7978845608028654f * (x + 0.044715f * x3));
    return 0.5f * x * (1.0f + t);
}

__device__ __forceinline__ uint32_t f2tf(float x) {
    uint32_t u;
    asm("cvt.rna.tf32.f32 %0, %1;" : "=r"(u) : "f"(x));
    return u;
}

// ---------------- weight pre-round: fp32 -> tf32(RNA) bits ----------------
__global__ void rnd_kernel(const float* __restrict__ src, float* __restrict__ dst, int n4)
{
    int i = blockIdx.x * 256 + threadIdx.x;
    if (i < n4) {
        float4 v = ((const float4*)src)[i];
        uint4 u = make_uint4(f2tf(v.x), f2tf(v.y), f2tf(v.z), f2tf(v.w));
        ((uint4*)dst)[i] = u;
    }
}

// ================= cp.async 5-stage TF32 GEMM =================
// C = A(MxK) @ B(KxN) + bias (+GELU). Block 128x256, BK=16, 8 warps (2x4), warp 64x64.
// A raw fp32 (HW-truncated to tf32), B pre-rounded RNA. smem: A[5][128][20], B[5][16][264].
#define PG_STAGES 5
#define PG_ASTAGE (128*20)          // floats
#define PG_BSTAGE (16*264)
#define PG_BBASE  (PG_STAGES*PG_ASTAGE*4)
#define PG_SMEM   (PG_STAGES*(PG_ASTAGE+PG_BSTAGE)*4)

__device__ __forceinline__ void cp16(uint32_t dst, const float* src, int sz) {
    asm volatile("cp.async.cg.shared.global [%0], [%1], 16, %2;"
                 :: "r"(dst), "l"(src), "r"(sz) : "memory");
}

template<int ACT>
__global__ void __launch_bounds__(256, 1)
pgemm_kernel(const float* __restrict__ A, const float* __restrict__ Bm,
             const float* __restrict__ bias, float* __restrict__ C,
             int M, int N, int K)
{
    extern __shared__ char dsm[];
    float* Asm = (float*)dsm;
    float* Bsm = (float*)(dsm + PG_BBASE);
    const uint32_t sbase = (uint32_t)__cvta_generic_to_shared(dsm);

    const int tid  = threadIdx.x;
    const int bm   = blockIdx.y * 128;
    const int bn   = blockIdx.x * 256;
    const int wid  = tid >> 5;
    const int lane = tid & 31;
    const int wm   = (wid & 1) * 64;
    const int wn   = (wid >> 1) * 64;
    const int g    = lane >> 2;
    const int tig  = lane & 3;

    float acc[4][8][4];
#pragma unroll
    for (int i = 0; i < 4; i++)
#pragma unroll
        for (int j = 0; j < 8; j++)
#pragma unroll
            for (int c = 0; c < 4; c++) acc[i][j][c] = 0.f;

    // producer coords
    const int arow = tid >> 1;
    const int acb  = (tid & 1) * 8;
    const bool aval = (bm + arow) < M;
    const float* Asrc = A + (size_t)(aval ? (bm + arow) : 0) * K + acb;
    const uint32_t adst = sbase + (arow * 20 + acb) * 4;
    const int asz = aval ? 16 : 0;

    const int bkr = tid >> 4;
    const int bn0 = (tid & 15) * 4;
    const float* Bsrc = Bm + (size_t)bkr * N + bn + bn0;
    const uint32_t bdst = sbase + PG_BBASE + (bkr * 264 + bn0) * 4;

    const int nk = K / 16;

#define PG_ISSUE(kt, s)                                                        \
    {                                                                          \
        const float* as_ = Asrc + (kt) * 16;                                   \
        uint32_t ad_ = adst + (s) * (PG_ASTAGE * 4);                           \
        cp16(ad_, as_, asz); cp16(ad_ + 16, as_ + 4, asz);                     \
        const float* bs_ = Bsrc + (size_t)(kt) * 16 * N;                       \
        uint32_t bd_ = bdst + (s) * (PG_BSTAGE * 4);                           \
        cp16(bd_,       bs_,       16); cp16(bd_ + 256, bs_ + 64,  16);        \
        cp16(bd_ + 512, bs_ + 128, 16); cp16(bd_ + 768, bs_ + 192, 16);        \
    }

    // prologue: tiles 0..3 into stages 0..3
#pragma unroll
    for (int s = 0; s < PG_STAGES - 1; s++) {
        PG_ISSUE(s, s);
        asm volatile("cp.async.commit_group;" ::: "memory");
    }

    for (int kt = 0; kt < nk; kt++) {
        const int buf = kt % PG_STAGES;
        asm volatile("cp.async.wait_group %0;" :: "n"(PG_STAGES - 2) : "memory");
        __syncthreads();

        const int nt = kt + PG_STAGES - 1;
        if (nt < nk) { PG_ISSUE(nt, nt % PG_STAGES); }
        asm volatile("cp.async.commit_group;" ::: "memory");

        const float* Ab = Asm + buf * PG_ASTAGE;
        const float* Bb = Bsm + buf * PG_BSTAGE;
#pragma unroll
        for (int kk = 0; kk < 2; kk++) {
            const float* br0 = Bb + (kk * 8 + tig) * 264;
            const float* br1 = Bb + (kk * 8 + tig + 4) * 264;
            uint32_t bf0[8], bf1[8];
#pragma unroll
            for (int j = 0; j < 8; j++) {
                const int n0 = wn + j * 8 + g;
                bf0[j] = __float_as_uint(br0[n0]);
                bf1[j] = __float_as_uint(br1[n0]);
            }
#pragma unroll
            for (int i = 0; i < 4; i++) {
                const float* ar = Ab + (wm + i * 16 + g) * 20 + kk * 8 + tig;
                uint32_t a0 = __float_as_uint(ar[0]);
                uint32_t a1 = __float_as_uint(ar[160]);
                uint32_t a2 = __float_as_uint(ar[4]);
                uint32_t a3 = __float_as_uint(ar[164]);
#pragma unroll
                for (int j = 0; j < 8; j++) {
                    asm volatile(
                        "mma.sync.aligned.m16n8k8.row.col.f32.tf32.tf32.f32 "
                        "{%0,%1,%2,%3}, {%4,%5,%6,%7}, {%8,%9}, {%0,%1,%2,%3};"
                        : "+f"(acc[i][j][0]), "+f"(acc[i][j][1]),
                          "+f"(acc[i][j][2]), "+f"(acc[i][j][3])
                        : "r"(a0), "r"(a1), "r"(a2), "r"(a3),
                          "r"(bf0[j]), "r"(bf1[j]));
                }
            }
        }
    }

    // epilogue
#pragma unroll
    for (int i = 0; i < 4; i++) {
        const int r0 = bm + wm + i * 16 + g;
        const int r1 = r0 + 8;
#pragma unroll
        for (int j = 0; j < 8; j++) {
            const int col = bn + wn + j * 8 + 2 * tig;
            const float bv0 = bias[col];
            const float bv1 = bias[col + 1];
            float v0a = acc[i][j][0] + bv0;
            float v1a = acc[i][j][1] + bv1;
            float v2a = acc[i][j][2] + bv0;
            float v3a = acc[i][j][3] + bv1;
            if (ACT == 1) { v0a = gelu_f(v0a); v1a = gelu_f(v1a); v2a = gelu_f(v2a); v3a = gelu_f(v3a); }
            if (r0 < M) *(float2*)&C[(size_t)r0 * N + col] = make_float2(v0a, v1a);
            if (r1 < M) *(float2*)&C[(size_t)r1 * N + col] = make_float2(v2a, v3a);
        }
    }
}

// ---------------- RNA register-staged TF32 GEMM (conv only) ----------------
template<int ACT>
__global__ void __launch_bounds__(256, 1)
tgemm_kernel(const float* __restrict__ A, const float* __restrict__ Bm,
             const float* __restrict__ bias, float* __restrict__ C,
             int M, int N, int K)
{
    extern __shared__ char dsm[];
    uint32_t (*As)[2048]    = (uint32_t (*)[2048])dsm;
    uint32_t (*Bs)[16][264] = (uint32_t (*)[16][264])(dsm + 16384);

    const int tid  = threadIdx.x;
    const int bm   = blockIdx.y * 128;
    const int bn   = blockIdx.x * 256;
    const int wid  = tid >> 5;
    const int lane = tid & 31;
    const int wm   = (wid & 1) * 64;
    const int wn   = (wid >> 1) * 64;
    const int g    = lane >> 2;
    const int tig  = lane & 3;

    float acc[4][8][4];
#pragma unroll
    for (int i = 0; i < 4; i++)
#pragma unroll
        for (int j = 0; j < 8; j++)
#pragma unroll
            for (int c = 0; c < 4; c++) acc[i][j][c] = 0.f;

    const int p   = tid & 31;
    const int mb  = (tid >> 5) & 7;
    const int gA  = p >> 2;
    const int tA  = p & 3;
    const int mlo = mb * 16 + gA;
    const int mhi = mlo + 8;
    const bool v0 = (bm + mlo) < M;
    const bool v1 = (bm + mhi) < M;
    const float* Alo = A + (size_t)(v0 ? (bm + mlo) : 0) * K;
    const float* Ahi = A + (size_t)(v1 ? (bm + mhi) : 0) * K;
    const int aoff0 = ((0 * 8 + mb) * 32 + p) * 4;
    const int aoff1 = ((1 * 8 + mb) * 32 + p) * 4;

    const int br  = tid >> 6;
    const int bc4 = (tid & 63) << 2;
    const float* Bbase = Bm + bn + bc4;

    const int nk = K / 16;

    {
#pragma unroll
        for (int kk = 0; kk < 2; kk++) {
            const int kl = kk * 8 + tA;
            float x00 = v0 ? Alo[kl]     : 0.f;
            float x01 = v0 ? Alo[kl + 4] : 0.f;
            float x10 = v1 ? Ahi[kl]     : 0.f;
            float x11 = v1 ? Ahi[kl + 4] : 0.f;
            uint32_t* dst = &As[0][kk ? aoff1 : aoff0];
            dst[0] = f2tf(x00); dst[1] = f2tf(x10);
            dst[2] = f2tf(x01); dst[3] = f2tf(x11);
        }
#pragma unroll
        for (int m = 0; m < 4; m++) {
            const int row = br + 4 * m;
            float4 b = *(const float4*)(Bbase + (size_t)row * N);
            *(uint4*)&Bs[0][row][bc4] = make_uint4(f2tf(b.x), f2tf(b.y), f2tf(b.z), f2tf(b.w));
        }
    }
    __syncthreads();

    for (int kt = 0; kt < nk; kt++) {
        const int cur = kt & 1;
        const bool have_next = (kt + 1 < nk);

        float na[2][4];
        float4 nb[4];
        if (have_next) {
            const int off = (kt + 1) * 16;
#pragma unroll
            for (int kk = 0; kk < 2; kk++) {
                const int kl = off + kk * 8 + tA;
                na[kk][0] = v0 ? Alo[kl]     : 0.f;
                na[kk][1] = v1 ? Ahi[kl]     : 0.f;
                na[kk][2] = v0 ? Alo[kl + 4] : 0.f;
                na[kk][3] = v1 ? Ahi[kl + 4] : 0.f;
            }
#pragma unroll
            for (int m = 0; m < 4; m++)
                nb[m] = *(const float4*)(Bbase + (size_t)(off + br + 4 * m) * N);
        }

#pragma unroll
        for (int kk = 0; kk < 2; kk++) {
            const uint32_t* brow0 = &Bs[cur][kk * 8 + tig][0];
            const uint32_t* brow1 = &Bs[cur][kk * 8 + tig + 4][0];
            uint32_t bf0[8], bf1[8];
#pragma unroll
            for (int j = 0; j < 8; j++) {
                const int n0 = wn + j * 8 + g;
                bf0[j] = brow0[n0];
                bf1[j] = brow1[n0];
            }
#pragma unroll
            for (int i = 0; i < 4; i++) {
                const int mbi = (wm >> 4) + i;
                uint4 af = *(const uint4*)&As[cur][((kk * 8 + mbi) * 32 + lane) * 4];
#pragma unroll
                for (int j = 0; j < 8; j++) {
                    asm volatile(
                        "mma.sync.aligned.m16n8k8.row.col.f32.tf32.tf32.f32 "
                        "{%0,%1,%2,%3}, {%4,%5,%6,%7}, {%8,%9}, {%0,%1,%2,%3};"
                        : "+f"(acc[i][j][0]), "+f"(acc[i][j][1]),
                          "+f"(acc[i][j][2]), "+f"(acc[i][j][3])
                        : "r"(af.x), "r"(af.y), "r"(af.z), "r"(af.w),
                          "r"(bf0[j]), "r"(bf1[j]));
                }
            }
        }

        if (have_next) {
            const int nxt = cur ^ 1;
#pragma unroll
            for (int kk = 0; kk < 2; kk++) {
                uint32_t* dst = &As[nxt][kk ? aoff1 : aoff0];
                dst[0] = f2tf(na[kk][0]); dst[1] = f2tf(na[kk][1]);
                dst[2] = f2tf(na[kk][2]); dst[3] = f2tf(na[kk][3]);
            }
#pragma unroll
            for (int m = 0; m < 4; m++) {
                const int row = br + 4 * m;
                *(uint4*)&Bs[nxt][row][bc4] =
                    make_uint4(f2tf(nb[m].x), f2tf(nb[m].y), f2tf(nb[m].z), f2tf(nb[m].w));
            }
        }
        __syncthreads();
    }

#pragma unroll
    for (int i = 0; i < 4; i++) {
        const int r0 = bm + wm + i * 16 + g;
        const int r1 = r0 + 8;
#pragma unroll
        for (int j = 0; j < 8; j++) {
            const int col = bn + wn + j * 8 + 2 * tig;
            const float bv0 = bias[col];
            const float bv1 = bias[col + 1];
            float v0a = acc[i][j][0] + bv0;
            float v1a = acc[i][j][1] + bv1;
            float v2a = acc[i][j][2] + bv0;
            float v3a = acc[i][j][3] + bv1;
            if (ACT == 1) { v0a = gelu_f(v0a); v1a = gelu_f(v1a); v2a = gelu_f(v2a); v3a = gelu_f(v3a); }
            if (r0 < M) *(float2*)&C[(size_t)r0 * N + col] = make_float2(v0a, v1a);
            if (r1 < M) *(float2*)&C[(size_t)r1 * N + col] = make_float2(v2a, v3a);
        }
    }
}

#define GEMM_SMEM (16384 + 2*16*264*4)

// ---------------- assemble h ----------------
__global__ void assemble_kernel(const float* __restrict__ x,
                                const float* __restrict__ rnd,
                                const int*   __restrict__ perm,
                                const float* __restrict__ mask_tok,
                                const float* __restrict__ agg_tok,
                                const float* __restrict__ pos_emb,
                                float* __restrict__ h,
                                float* __restrict__ mask_pos)
{
    int row = blockIdx.x;
    int b   = row / SEQ;
    int sp  = row - b * SEQ;
    int tid = threadIdx.x;
    float* hp = h + (size_t)row * D_;

    if (sp == 0) {
        hp[tid]       = agg_tok[tid];
        hp[tid + 256] = agg_tok[tid + 256];
        hp[tid + 512] = agg_tok[tid + 512];
        return;
    }
    int s = sp - 1;
    int i = b * S_ + s;
    float r0 = rnd[i * 3 + 0];
    float r1 = rnd[i * 3 + 1];
    float r2 = rnd[i * 3 + 2];
    bool  sel = (r0 <= 0.2f);
    float m  = (sel && r1 <= 0.8f) ? 1.f : 0.f;
    float rd = (sel && r1 > 0.8f && r2 <= 0.5f) ? 1.f : 0.f;
    if (tid == 0) mask_pos[i] = sel ? 1.f : 0.f;

    int pi = perm[i];
    const float* xp = x + (size_t)i  * D_;
    const float* sh = x + (size_t)pi * D_;
    const float* pe = pos_emb + (size_t)s * D_;
    float keep = 1.f - m - rd;

#pragma unroll
    for (int e = 0; e < 3; e++) {
        int d = tid + e * 256;
        hp[d] = xp[d] * keep + mask_tok[d] * m + sh[d] * rd + pe[d];
    }
}

// ---------------- attention ----------------
__global__ void __launch_bounds__(256)
attn_kernel(const float* __restrict__ Q, const float* __restrict__ K,
            const float* __restrict__ V, float* __restrict__ O)
{
    extern __shared__ float sm[];
    float* Kt    = sm;
    float* Vs    = Kt + 64 * 257;
    float* probs = Vs + 257 * 64;
    float* qbuf  = probs + 8 * 257;

    int hh = blockIdx.x;
    int bb = blockIdx.y;
    int tid = threadIdx.x;
    const size_t base = ((size_t)bb * SEQ) * D_ + (size_t)hh * DKH;

    for (int idx = tid; idx < SEQ * DKH; idx += 256) {
        int k = idx >> 6;
        int d = idx & 63;
        float kv = K[base + (size_t)k * D_ + d];
        Kt[d * SEQ + k] = kv;
        Vs[idx] = V[base + (size_t)k * D_ + d];
    }
    __syncthreads();

    int w = tid >> 5, lane = tid & 31;
    float* qw = qbuf + w * 64;
    float* pw = probs + w * SEQ;

    for (int q = w; q < SEQ; q += 8) {
        const float* qp = Q + base + (size_t)q * D_;
        qw[lane]      = qp[lane];
        qw[lane + 32] = qp[lane + 32];
        __syncwarp();

        float s[9];
#pragma unroll
        for (int j = 0; j < 9; j++) s[j] = 0.f;

#pragma unroll 4
        for (int d = 0; d < 64; d++) {
            float qv = qw[d];
            const float* kr = &Kt[d * SEQ + lane];
#pragma unroll
            for (int j = 0; j < 9; j++)
                s[j] += qv * kr[j * 32];
        }

        float mx = -1e30f;
#pragma unroll
        for (int j = 0; j < 9; j++) {
            int k = lane + j * 32;
            s[j] = (k < SEQ) ? s[j] * 0.125f : -1e30f;
            mx = fmaxf(mx, s[j]);
        }
        for (int off = 16; off; off >>= 1)
            mx = fmaxf(mx, __shfl_xor_sync(0xffffffffu, mx, off));

        float sum = 0.f;
#pragma unroll
        for (int j = 0; j < 9; j++) {
            float e = __expf(s[j] - mx);
            sum += e;
            s[j] = e;
        }
        for (int off = 16; off; off >>= 1)
            sum += __shfl_xor_sync(0xffffffffu, sum, off);
        float inv = 1.f / sum;
#pragma unroll
        for (int j = 0; j < 9; j++) {
            int k = lane + j * 32;
            if (k < SEQ) pw[k] = s[j] * inv;
        }
        __syncwarp();

        float o0 = 0.f, o1 = 0.f;
#pragma unroll 4
        for (int k = 0; k < SEQ; k++) {
            float pv = pw[k];
            float2 v2 = *(const float2*)&Vs[k * 64 + 2 * lane];
            o0 += pv * v2.x;
            o1 += pv * v2.y;
        }
        *(float2*)&O[base + (size_t)q * D_ + 2 * lane] = make_float2(o0, o1);
        __syncwarp();
    }
}

// ---------------- residual + LayerNorm ----------------
__global__ void add_ln_kernel(const float* __restrict__ H, const float* __restrict__ Dl,
                              const float* __restrict__ g, const float* __restrict__ be,
                              float* __restrict__ Out)
{
    int row = blockIdx.x, tid = threadIdx.x;
    const float* hp = H  + (size_t)row * D_;
    const float* dp = Dl + (size_t)row * D_;
    float v0 = hp[tid]       + dp[tid];
    float v1 = hp[tid + 256] + dp[tid + 256];
    float v2 = hp[tid + 512] + dp[tid + 512];

    __shared__ float red[8];
    __shared__ float s_mu, s_var;
    int lane = tid & 31, w = tid >> 5;

    float s = v0 + v1 + v2;
    for (int off = 16; off; off >>= 1) s += __shfl_xor_sync(0xffffffffu, s, off);
    if (lane == 0) red[w] = s;
    __syncthreads();
    if (tid == 0) {
        float t = 0.f;
        for (int i = 0; i < 8; i++) t += red[i];
        s_mu = t * (1.0f / 768.0f);
    }
    __syncthreads();
    float mu = s_mu;
    float d0 = v0 - mu, d1 = v1 - mu, d2 = v2 - mu;
    float qv = d0 * d0 + d1 * d1 + d2 * d2;
    for (int off = 16; off; off >>= 1) qv += __shfl_xor_sync(0xffffffffu, qv, off);
    if (lane == 0) red[w] = qv;
    __syncthreads();
    if (tid == 0) {
        float t = 0.f;
        for (int i = 0; i < 8; i++) t += red[i];
        s_var = t * (1.0f / 768.0f);
    }
    __syncthreads();
    float rs = rsqrtf(s_var + 1e-6f);

    float* op = Out + (size_t)row * D_;
    op[tid]       = d0 * rs * g[tid]       + be[tid];
    op[tid + 256] = d1 * rs * g[tid + 256] + be[tid + 256];
    op[tid + 512] = d2 * rs * g[tid + 512] + be[tid + 512];
}

// ---------------- scatter ----------------
__global__ void writeout_kernel(const float* __restrict__ h,
                                float* __restrict__ agg, float* __restrict__ pred)
{
    size_t idx = (size_t)blockIdx.x * 256 + threadIdx.x;
    if (idx >= (size_t)ROWS * D_) return;
    int row = (int)(idx / D_);
    int d   = (int)(idx - (size_t)row * D_);
    int b   = row / SEQ;
    int sp  = row - b * SEQ;
    float val = h[idx];
    if (sp == 0) agg[(size_t)b * D_ + d] = val;
    else pred[((size_t)(b * S_ + sp - 1)) * D_ + d] = val;
}

// ---------------- host ----------------
static inline void run_pgemm(const float* A, const float* Bw, const float* bias,
                             float* C, int M, int N, int K, bool gelu)
{
    dim3 grid(N / 256, (M + 127) / 128);
    if (gelu) pgemm_kernel<1><<<grid, 256, PG_SMEM>>>(A, Bw, bias, C, M, N, K);
    else      pgemm_kernel<0><<<grid, 256, PG_SMEM>>>(A, Bw, bias, C, M, N, K);
}

extern "C" void kernel_launch(void* const* d_in, const int* in_sizes, int n_in,
                              void* d_out, int out_size)
{
    const float* inputs     = (const float*)d_in[0];
    const float* randomness = (const float*)d_in[1];
    const int*   perm       = (const int*)  d_in[2];
    const float* conv_w     = (const float*)d_in[3];
    const float* conv_b     = (const float*)d_in[4];
    const float* pos_emb    = (const float*)d_in[5];
    const float* mask_tok   = (const float*)d_in[6];
    const float* agg_tok    = (const float*)d_in[7];
    const float* wq  = (const float*)d_in[8];
    const float* bq  = (const float*)d_in[9];
    const float* wk  = (const float*)d_in[10];
    const float* bk  = (const float*)d_in[11];
    const float* wv  = (const float*)d_in[12];
    const float* bv  = (const float*)d_in[13];
    const float* wo  = (const float*)d_in[14];
    const float* bo  = (const float*)d_in[15];
    const float* ln1g = (const float*)d_in[16];
    const float* ln1b = (const float*)d_in[17];
    const float* w1  = (const float*)d_in[18];
    const float* b1  = (const float*)d_in[19];
    const float* w2  = (const float*)d_in[20];
    const float* b2  = (const float*)d_in[21];
    const float* ln2g = (const float*)d_in[22];
    const float* ln2b = (const float*)d_in[23];

    float* out      = (float*)d_out;
    float* out_agg  = out;
    float* out_pred = out + 49152;
    float* out_mask = out + 12632064;
    float* out_emb  = out + 12648448;

    float *h, *q, *k, *v, *o, *t, *f, *wr;
    cudaGetSymbolAddress((void**)&h, g_h);
    cudaGetSymbolAddress((void**)&q, g_q);
    cudaGetSymbolAddress((void**)&k, g_k);
    cudaGetSymbolAddress((void**)&v, g_v);
    cudaGetSymbolAddress((void**)&o, g_o);
    cudaGetSymbolAddress((void**)&t, g_t);
    cudaGetSymbolAddress((void**)&f, g_f);
    cudaGetSymbolAddress((void**)&wr, g_wr);

    cudaFuncSetAttribute(tgemm_kernel<0>, cudaFuncAttributeMaxDynamicSharedMemorySize, GEMM_SMEM);
    cudaFuncSetAttribute(pgemm_kernel<0>, cudaFuncAttributeMaxDynamicSharedMemorySize, PG_SMEM);
    cudaFuncSetAttribute(pgemm_kernel<1>, cudaFuncAttributeMaxDynamicSharedMemorySize, PG_SMEM);

    // pre-round weights to tf32 RNA
    rnd_kernel<<<1152, 256>>>(wq, wr + RQ_OFF, 294912);
    rnd_kernel<<<1152, 256>>>(wk, wr + RK_OFF, 294912);
    rnd_kernel<<<1152, 256>>>(wv, wr + RV_OFF, 294912);
    rnd_kernel<<<1152, 256>>>(wo, wr + RO_OFF, 294912);
    rnd_kernel<<<4608, 256>>>(w1, wr + R1_OFF, 1179648);
    rnd_kernel<<<4608, 256>>>(w2, wr + R2_OFF, 1179648);

    // conv (stride == kernel => pure GEMM), RNA path, writes embeddings directly
    {
        dim3 grid(D_ / 256, (BSR + 127) / 128);
        tgemm_kernel<0><<<grid, 256, GEMM_SMEM>>>(inputs, conv_w, conv_b, out_emb, BSR, D_, 512);
    }

    assemble_kernel<<<ROWS, 256>>>(out_emb, randomness, perm, mask_tok, agg_tok,
                                   pos_emb, h, out_mask);

    const int SMEM_ATTN = (64 * SEQ + SEQ * 64 + 8 * SEQ + 8 * 64) * (int)sizeof(float);
    cudaFuncSetAttribute(attn_kernel, cudaFuncAttributeMaxDynamicSharedMemorySize, SMEM_ATTN);

    for (int l = 0; l < 2; l++) {
        const float* wq_r = wr + RQ_OFF + (size_t)l * 589824;
        const float* wk_r = wr + RK_OFF + (size_t)l * 589824;
        const float* wv_r = wr + RV_OFF + (size_t)l * 589824;
        const float* wo_r = wr + RO_OFF + (size_t)l * 589824;
        const float* w1_r = wr + R1_OFF + (size_t)l * 2359296;
        const float* w2_r = wr + R2_OFF + (size_t)l * 2359296;

        run_pgemm(h, wq_r, bq + l * D_, q, ROWS, D_, D_, false);
        run_pgemm(h, wk_r, bk + l * D_, k, ROWS, D_, D_, false);
        run_pgemm(h, wv_r, bv + l * D_, v, ROWS, D_, D_, false);

        attn_kernel<<<dim3(HEADS, B_), 256, SMEM_ATTN>>>(q, k, v, o);

        run_pgemm(o, wo_r, bo + l * D_, t, ROWS, D_, D_, false);
        add_ln_kernel<<<ROWS, 256>>>(h, t, ln1g + l * D_, ln1b + l * D_, h);

        run_pgemm(h, w1_r, b1 + l * F_, f, ROWS, F_, D_, true);
        run_pgemm(f, w2_r, b2 + l * D_, t, ROWS, D_, F_, false);
        add_ln_kernel<<<ROWS, 256>>>(h, t, ln2g + l * D_, ln2b + l * D_, h);
    }

    int total = ROWS * D_;
    writeout_kernel<<<(total + 255) / 256, 256>>>(h, out_agg, out_pred);
}